// round 2
// baseline (speedup 1.0000x reference)
#include <cuda_runtime.h>
#include <cstddef>

#define D_IN  128
#define D_HID 128
#define D_OUT 32
#define NMAX  100000

// ---------------- static device scratch (no runtime allocation) ----------------
__device__ float  g_agg1[(size_t)NMAX * D_HID];   // 51.2 MB
__device__ float  g_h1  [(size_t)NMAX * D_HID];   // pre-BN h1 (BN fused into gemm2 load)
__device__ float  g_tr  [(size_t)NMAX * 64];      // [t | r2] = relu(bn(h1)) @ [W_rel2 | W_root2]
__device__ float  g_agg2[(size_t)NMAX * D_OUT];   // agg2 then h2pre in place
__device__ double g_stats[320];                   // sum1[128] sq1[128] sum2[32] sq2[32]
__device__ float  g_ss[320];                      // scale1[128] shift1[128] scale2[32] shift2[32]
__device__ float  g_wcat2[128 * 64];              // [W_rel2 | W_root2] column-concat
__device__ int    g_is64;

// ---------------- f32x2 packed-FMA helpers ----------------
__device__ __forceinline__ void fma_f32x2(unsigned long long& d,
                                          unsigned long long a,
                                          unsigned long long b,
                                          unsigned long long c) {
    asm("fma.rn.f32x2 %0, %1, %2, %3;" : "=l"(d) : "l"(a), "l"(b), "l"(c));
}
__device__ __forceinline__ unsigned long long dup_f32(float v) {
    unsigned long long r;
    asm("mov.b64 %0, {%1, %1};" : "=l"(r) : "f"(v));
    return r;
}

// ---------------- small utility kernels ----------------
__global__ void zero4_kernel(float* p, int n4) {
    int i = blockIdx.x * blockDim.x + threadIdx.x;
    int stride = gridDim.x * blockDim.x;
    float4 z = make_float4(0.f, 0.f, 0.f, 0.f);
    for (; i < n4; i += stride) ((float4*)p)[i] = z;
}

__global__ void zero_d_kernel(double* p, int n) {
    int i = blockIdx.x * blockDim.x + threadIdx.x;
    if (i < n) p[i] = 0.0;
}

// Detect whether edge_index buffer is int64 (odd 32-bit words all zero) or int32.
__global__ void detect_kernel(const int* ei, int E) {
    if (threadIdx.x != 0 || blockIdx.x != 0) return;
    int n = 2 * E;
    int allzero = 1;
    for (int k = 1; k < 256 && k < n; k += 2) {
        if (ei[k] != 0) { allzero = 0; break; }
    }
    g_is64 = allzero;
}

// Build column-concat [W_rel2 | W_root2] : [128][64]
__global__ void prep_w_kernel(const float* __restrict__ Wrel2,
                              const float* __restrict__ Wroot2,
                              float* __restrict__ wcat2) {
    int i = blockIdx.x * blockDim.x + threadIdx.x;
    if (i < 128 * 64) {
        int r = i >> 6, c = i & 63;
        wcat2[i] = (c < 32) ? Wrel2[r * 32 + c] : Wroot2[r * 32 + (c - 32)];
    }
}

// ---------------- edge scatter: agg[dst] += feat[src] (vectorized L2 reductions) ----------------
template <int LANES>  // LANES * 4 floats per edge row
__global__ void __launch_bounds__(256) scatter_kernel(
    const float* __restrict__ feat, int featStride,
    const void* __restrict__ eiv, int E,
    float* __restrict__ agg, int aggStride)
{
    int gid = blockIdx.x * 256 + threadIdx.x;
    int e = gid / LANES;
    bool valid = (e < E);
    int lane = threadIdx.x & 31;
    int j = lane & (LANES - 1);
    int grp = lane - j;

    int s = 0, d = 0;
    if (valid && j == 0) {
        if (g_is64) {
            const long long* p = (const long long*)eiv;
            s = (int)p[e];
            d = (int)p[(size_t)E + e];
        } else {
            const int* p = (const int*)eiv;
            s = p[e];
            d = p[E + e];
        }
    }
    s = __shfl_sync(0xffffffffu, s, grp);
    d = __shfl_sync(0xffffffffu, d, grp);
    if (!valid) return;

    const float4 v = *(const float4*)(feat + (size_t)s * featStride + (j << 2));
    float* a = agg + (size_t)d * aggStride + (j << 2);
    asm volatile("red.global.add.v4.f32 [%0], {%1,%2,%3,%4};"
                 :: "l"(a), "f"(v.x), "f"(v.y), "f"(v.z), "f"(v.w)
                 : "memory");
}

// ---------------- tiled GEMM with packed f32x2 FMA: C = Aa@Ba + Ab@Bb + bias ----------------
// A matrices: [M, Ka/Kb] row-major; B matrices: [K, BN] row-major (ld = BN).
// If BNRELU_A: A-tile elements pass through relu(scale[k]*v + shift[k]) on load.
template <int BN, int TN, bool BNRELU_A>
__global__ void __launch_bounds__(256) gemm_kernel(
    const float* __restrict__ Aa, const float* __restrict__ Ba, int Ka,
    const float* __restrict__ Ab, const float* __restrict__ Bb, int Kb,
    const float* __restrict__ bias, float* __restrict__ C, int M,
    const float* __restrict__ ascale, const float* __restrict__ ashift)
{
    constexpr int BM = 128, BK = 32, TM = 8;
    constexpr int NT = (BM / TM) * (BN / TN);  // 256
    constexpr int F4PR = BK / 4;               // float4 per A row chunk
    __shared__ float As[BK][BM + 4];
    __shared__ float Bs[BK][BN];

    const int tid = threadIdx.x;
    const int tx = tid % (BN / TN);
    const int ty = tid / (BN / TN);
    const int m0 = blockIdx.x * BM;

    unsigned long long acc2[TM][TN / 2];
#pragma unroll
    for (int i = 0; i < TM; i++)
#pragma unroll
        for (int j = 0; j < TN / 2; j++) acc2[i][j] = 0ULL;

    const int K = Ka + Kb;
    for (int kc = 0; kc < K; kc += BK) {
        const float* A; const float* B; int lda, kloc;
        if (kc < Ka) { A = Aa; B = Ba; lda = Ka; kloc = kc; }
        else         { A = Ab; B = Bb; lda = Kb; kloc = kc - Ka; }

        // load A tile (BM x BK) transposed into As[k][m]
#pragma unroll
        for (int t = 0; t < (BM * BK) / (4 * NT); t++) {
            int v = tid + t * NT;
            int row = v / F4PR;
            int c4 = (v % F4PR) << 2;
            float4 val = make_float4(0.f, 0.f, 0.f, 0.f);
            if (m0 + row < M)
                val = *(const float4*)(A + (size_t)(m0 + row) * lda + kloc + c4);
            if (BNRELU_A) {
                int kg = kloc + c4;
                val.x = fmaxf(fmaf(val.x, __ldg(&ascale[kg + 0]), __ldg(&ashift[kg + 0])), 0.f);
                val.y = fmaxf(fmaf(val.y, __ldg(&ascale[kg + 1]), __ldg(&ashift[kg + 1])), 0.f);
                val.z = fmaxf(fmaf(val.z, __ldg(&ascale[kg + 2]), __ldg(&ashift[kg + 2])), 0.f);
                val.w = fmaxf(fmaf(val.w, __ldg(&ascale[kg + 3]), __ldg(&ashift[kg + 3])), 0.f);
            }
            As[c4 + 0][row] = val.x;
            As[c4 + 1][row] = val.y;
            As[c4 + 2][row] = val.z;
            As[c4 + 3][row] = val.w;
        }
        // load B tile (BK x BN)
#pragma unroll
        for (int t = 0; t < (BK * BN) / (4 * NT); t++) {
            int v = tid + t * NT;
            int kr = v / (BN / 4);
            int c4 = (v % (BN / 4)) << 2;
            *(float4*)&Bs[kr][c4] = *(const float4*)(B + (size_t)(kloc + kr) * BN + c4);
        }
        __syncthreads();

#pragma unroll
        for (int k = 0; k < BK; k++) {
            float a[TM];
            unsigned long long aa[TM], bb[TN / 2];
#pragma unroll
            for (int i = 0; i < TM; i += 4)
                *(float4*)&a[i] = *(const float4*)&As[k][ty * TM + i];
#pragma unroll
            for (int j = 0; j < TN; j += 4) {
                ulonglong2 t2 = *(const ulonglong2*)&Bs[k][tx * TN + j];
                bb[j / 2] = t2.x;
                bb[j / 2 + 1] = t2.y;
            }
#pragma unroll
            for (int i = 0; i < TM; i++) aa[i] = dup_f32(a[i]);
#pragma unroll
            for (int i = 0; i < TM; i++)
#pragma unroll
                for (int j = 0; j < TN / 2; j++)
                    fma_f32x2(acc2[i][j], aa[i], bb[j], acc2[i][j]);
        }
        __syncthreads();
    }

    float bfr[TN];
#pragma unroll
    for (int j = 0; j < TN; j++) bfr[j] = bias ? bias[tx * TN + j] : 0.f;

#pragma unroll
    for (int i = 0; i < TM; i++) {
        int grow = m0 + ty * TM + i;
        if (grow < M) {
#pragma unroll
            for (int j = 0; j < TN; j += 4) {
                float2 p0 = *(float2*)&acc2[i][j / 2];
                float2 p1 = *(float2*)&acc2[i][j / 2 + 1];
                float4 v;
                v.x = p0.x + bfr[j + 0];
                v.y = p0.y + bfr[j + 1];
                v.z = p1.x + bfr[j + 2];
                v.w = p1.y + bfr[j + 3];
                *(float4*)(C + (size_t)grow * BN + tx * TN + j) = v;
            }
        }
    }
}

// ---------------- column stats (sum, sumsq) in double ----------------
__global__ void __launch_bounds__(256) stats_kernel(
    const float* __restrict__ h, long long n, int D,
    double* __restrict__ sum, double* __restrict__ sq)
{
    long long i = (long long)blockIdx.x * 256 + threadIdx.x;
    long long stride = (long long)gridDim.x * 256;
    double ls = 0.0, lq = 0.0;
    for (; i < n; i += stride) {
        float v = h[i];
        ls += v;
        lq += (double)v * v;
    }
    __shared__ double shA[256], shB[256];
    int tid = threadIdx.x;
    shA[tid] = ls; shB[tid] = lq;
    __syncthreads();
    for (int off = 128; off >= D; off >>= 1) {
        if (tid < off) { shA[tid] += shA[tid + off]; shB[tid] += shB[tid + off]; }
        __syncthreads();
    }
    if (tid < D) {
        atomicAdd(&sum[tid], shA[tid]);
        atomicAdd(&sq[tid], shB[tid]);
    }
}

// h2pre = agg2 + r2 + b_rel2 (in place into agg2) fused with column stats (D=32)
__global__ void __launch_bounds__(256) combine_stats_kernel(
    float* __restrict__ agg2, const float* __restrict__ tr,
    const float* __restrict__ b, long long n,
    double* __restrict__ sum, double* __restrict__ sq)
{
    long long i = (long long)blockIdx.x * 256 + threadIdx.x;
    long long stride = (long long)gridDim.x * 256;
    int col = (int)(i & 31);
    float bias = b[col];
    double ls = 0.0, lq = 0.0;
    for (; i < n; i += stride) {
        long long row = i >> 5;
        int c = (int)(i & 31);
        float v = agg2[i] + __ldg(&tr[row * 64 + 32 + c]) + bias;
        agg2[i] = v;
        ls += v;
        lq += (double)v * v;
    }
    __shared__ double shA[256], shB[256];
    int tid = threadIdx.x;
    shA[tid] = ls; shB[tid] = lq;
    __syncthreads();
    for (int off = 128; off >= 32; off >>= 1) {
        if (tid < off) { shA[tid] += shA[tid + off]; shB[tid] += shB[tid + off]; }
        __syncthreads();
    }
    if (tid < 32) {
        atomicAdd(&sum[tid], shA[tid]);
        atomicAdd(&sq[tid], shB[tid]);
    }
}

// per-column BN affine coefficients
__global__ void bn_finalize_kernel(
    const double* __restrict__ sum, const double* __restrict__ sq,
    const float* __restrict__ gamma, const float* __restrict__ beta,
    float* __restrict__ scale, float* __restrict__ shift, float invM)
{
    int c = threadIdx.x;
    double mu = sum[c] * (double)invM;
    double var = sq[c] * (double)invM - mu * mu;
    float s = gamma[c] * rsqrtf((float)var + 1e-5f);
    scale[c] = s;
    shift[c] = beta[c] - (float)mu * s;
}

__global__ void __launch_bounds__(256) bn_relu_kernel(
    const float* __restrict__ in, float* __restrict__ out, long long n, int mask,
    const float* __restrict__ scale, const float* __restrict__ shift)
{
    long long i = (long long)blockIdx.x * blockDim.x + threadIdx.x;
    long long stride = (long long)gridDim.x * blockDim.x;
    for (; i < n; i += stride) {
        int c = (int)(i & mask);
        float v = fmaf(in[i], __ldg(&scale[c]), __ldg(&shift[c]));
        out[i] = fmaxf(v, 0.f);
    }
}

static inline int ceil_div_i(int a, int b) { return (a + b - 1) / b; }

// ---------------- launch ----------------
extern "C" void kernel_launch(void* const* d_in, const int* in_sizes, int n_in,
                              void* d_out, int out_size)
{
    const float* x      = (const float*)d_in[0];
    const void*  ei     = d_in[1];
    const float* Wrel1  = (const float*)d_in[2];
    const float* brel1  = (const float*)d_in[3];
    const float* Wroot1 = (const float*)d_in[4];
    const float* gamma1 = (const float*)d_in[5];
    const float* beta1  = (const float*)d_in[6];
    const float* Wrel2  = (const float*)d_in[7];
    const float* brel2  = (const float*)d_in[8];
    const float* Wroot2 = (const float*)d_in[9];
    const float* gamma2 = (const float*)d_in[10];
    const float* beta2  = (const float*)d_in[11];

    const int N = in_sizes[0] / D_IN;
    const int E = in_sizes[1] / 2;

    float *agg1, *h1, *tr, *agg2, *ss, *wcat2;
    double* stats;
    cudaGetSymbolAddress((void**)&agg1, g_agg1);
    cudaGetSymbolAddress((void**)&h1, g_h1);
    cudaGetSymbolAddress((void**)&tr, g_tr);
    cudaGetSymbolAddress((void**)&agg2, g_agg2);
    cudaGetSymbolAddress((void**)&stats, g_stats);
    cudaGetSymbolAddress((void**)&ss, g_ss);
    cudaGetSymbolAddress((void**)&wcat2, g_wcat2);

    detect_kernel<<<1, 32>>>((const int*)ei, E);
    zero4_kernel<<<2048, 256>>>(agg1, N * D_HID / 4);
    zero4_kernel<<<512, 256>>>(agg2, N * D_OUT / 4);
    zero_d_kernel<<<2, 256>>>(stats, 320);
    prep_w_kernel<<<32, 256>>>(Wrel2, Wroot2, wcat2);

    // Layer 1: aggregate x in 128-d, then [agg1|x] @ [W_rel1;W_root1] + b_rel1
    {
        long long t = (long long)E * 32;
        int blocks = (int)((t + 255) / 256);
        scatter_kernel<32><<<blocks, 256>>>(x, D_IN, ei, E, agg1, D_HID);
    }
    gemm_kernel<128, 8, false><<<ceil_div_i(N, 128), 256>>>(
        agg1, Wrel1, D_HID, x, Wroot1, D_IN, brel1, h1, N, nullptr, nullptr);

    // BN1 stats on pre-BN h1; normalize+relu fused into gemm2's A-load
    stats_kernel<<<512, 256>>>(h1, (long long)N * D_HID, D_HID, stats, stats + 128);
    bn_finalize_kernel<<<1, 128>>>(stats, stats + 128, gamma1, beta1, ss, ss + 128, 1.0f / (float)N);

    // Layer 2: project FIRST (t = relu(bn(h1))@W_rel2 | @W_root2), then scatter t in 32-d
    gemm_kernel<64, 4, true><<<ceil_div_i(N, 128), 256>>>(
        h1, wcat2, D_HID, nullptr, nullptr, 0, nullptr, tr, N, ss, ss + 128);
    {
        long long t = (long long)E * 8;
        int blocks = (int)((t + 255) / 256);
        scatter_kernel<8><<<blocks, 256>>>(tr, 64, ei, E, agg2, D_OUT);
    }
    combine_stats_kernel<<<512, 256>>>(agg2, tr, brel2, (long long)N * D_OUT,
                                       stats + 256, stats + 288);
    bn_finalize_kernel<<<1, 32>>>(stats + 256, stats + 288, gamma2, beta2,
                                  ss + 256, ss + 288, 1.0f / (float)N);
    bn_relu_kernel<<<1024, 256>>>(agg2, (float*)d_out, (long long)N * D_OUT, D_OUT - 1,
                                  ss + 256, ss + 288);
}

// round 3
// speedup vs baseline: 1.4668x; 1.4668x over previous
#include <cuda_runtime.h>
#include <cstddef>

#define D_IN  128
#define D_HID 128
#define D_OUT 32
#define NMAX  100000

// ---------------- static device scratch (no runtime allocation) ----------------
__device__ float  g_agg1[(size_t)NMAX * D_HID];   // 51.2 MB
__device__ float  g_h1  [(size_t)NMAX * D_HID];   // h1 = x@Wroot1+b, then += agg1@Wrel1
__device__ float  g_tr  [(size_t)NMAX * 64];      // [t | r2] = relu(bn(h1)) @ [W_rel2 | W_root2]
__device__ float  g_agg2[(size_t)NMAX * D_OUT];   // agg2 then h2pre in place
__device__ double g_stats[320];                   // sum1[128] sq1[128] sum2[32] sq2[32]
__device__ float  g_ss[320];                      // scale1[128] shift1[128] scale2[32] shift2[32]
__device__ float  g_wcat2[128 * 64];              // [W_rel2 | W_root2] column-concat
__device__ int    g_is64;

// ---------------- small utility kernels ----------------
__global__ void zero4_kernel(float* p, int n4) {
    int i = blockIdx.x * blockDim.x + threadIdx.x;
    int stride = gridDim.x * blockDim.x;
    float4 z = make_float4(0.f, 0.f, 0.f, 0.f);
    for (; i < n4; i += stride) ((float4*)p)[i] = z;
}

__global__ void zero_d_kernel(double* p, int n) {
    int i = blockIdx.x * blockDim.x + threadIdx.x;
    if (i < n) p[i] = 0.0;
}

// Detect whether edge_index buffer is int64 (odd 32-bit words all zero) or int32.
__global__ void detect_kernel(const int* ei, int E) {
    if (threadIdx.x != 0 || blockIdx.x != 0) return;
    int n = 2 * E;
    int allzero = 1;
    for (int k = 1; k < 256 && k < n; k += 2) {
        if (ei[k] != 0) { allzero = 0; break; }
    }
    g_is64 = allzero;
}

// Build column-concat [W_rel2 | W_root2] : [128][64]
__global__ void prep_w_kernel(const float* __restrict__ Wrel2,
                              const float* __restrict__ Wroot2,
                              float* __restrict__ wcat2) {
    int i = blockIdx.x * blockDim.x + threadIdx.x;
    if (i < 128 * 64) {
        int r = i >> 6, c = i & 63;
        wcat2[i] = (c < 32) ? Wrel2[r * 32 + c] : Wroot2[r * 32 + (c - 32)];
    }
}

// ---------------- edge scatter: agg[dst] += feat[src] (vectorized L2 reductions) ----------------
template <int LANES>  // LANES * 4 floats per edge row
__global__ void __launch_bounds__(256) scatter_kernel(
    const float* __restrict__ feat, int featStride,
    const void* __restrict__ eiv, int E,
    float* __restrict__ agg, int aggStride)
{
    int gid = blockIdx.x * 256 + threadIdx.x;
    int e = gid / LANES;
    bool valid = (e < E);
    int lane = threadIdx.x & 31;
    int j = lane & (LANES - 1);
    int grp = lane - j;

    int s = 0, d = 0;
    if (valid && j == 0) {
        if (g_is64) {
            const long long* p = (const long long*)eiv;
            s = (int)p[e];
            d = (int)p[(size_t)E + e];
        } else {
            const int* p = (const int*)eiv;
            s = p[e];
            d = p[E + e];
        }
    }
    s = __shfl_sync(0xffffffffu, s, grp);
    d = __shfl_sync(0xffffffffu, d, grp);
    if (!valid) return;

    const float4 v = *(const float4*)(feat + (size_t)s * featStride + (j << 2));
    float* a = agg + (size_t)d * aggStride + (j << 2);
    asm volatile("red.global.add.v4.f32 [%0], {%1,%2,%3,%4};"
                 :: "l"(a), "f"(v.x), "f"(v.y), "f"(v.z), "f"(v.w)
                 : "memory");
}

// ---------------- tiled scalar-FMA GEMM: C (+)= A@B (+ bias) ----------------
// A: [M, Ka] row-major; B: [Ka, BN] row-major (ld = BN).
// ACCUM: C += result. BNRELU: A elements pass relu(scale[k]*v+shift[k]) on load.
template <int BN, int TN, bool ACCUM, bool BNRELU>
__global__ void __launch_bounds__(256) gemm_kernel(
    const float* __restrict__ A, const float* __restrict__ B, int Ka,
    const float* __restrict__ bias, float* __restrict__ C, int M,
    const float* __restrict__ ascale, const float* __restrict__ ashift)
{
    constexpr int BM = 128, BK = 16, TM = 8;
    constexpr int NT = (BM / TM) * (BN / TN);  // 256
    __shared__ float As[BK][BM + 4];
    __shared__ float Bs[BK][BN];

    const int tid = threadIdx.x;
    const int tx = tid % (BN / TN);
    const int ty = tid / (BN / TN);
    const int m0 = blockIdx.x * BM;

    float acc[TM][TN];
#pragma unroll
    for (int i = 0; i < TM; i++)
#pragma unroll
        for (int j = 0; j < TN; j++) acc[i][j] = 0.f;

    for (int kc = 0; kc < Ka; kc += BK) {
        // load A tile (BM x BK) transposed into As[k][m]
#pragma unroll
        for (int t = 0; t < (BM * BK) / (4 * NT); t++) {
            int v = tid + t * NT;
            int row = v >> 2;
            int c4 = (v & 3) << 2;
            float4 val = make_float4(0.f, 0.f, 0.f, 0.f);
            if (m0 + row < M)
                val = *(const float4*)(A + (size_t)(m0 + row) * Ka + kc + c4);
            if (BNRELU) {
                int kg = kc + c4;
                val.x = fmaxf(fmaf(val.x, __ldg(&ascale[kg + 0]), __ldg(&ashift[kg + 0])), 0.f);
                val.y = fmaxf(fmaf(val.y, __ldg(&ascale[kg + 1]), __ldg(&ashift[kg + 1])), 0.f);
                val.z = fmaxf(fmaf(val.z, __ldg(&ascale[kg + 2]), __ldg(&ashift[kg + 2])), 0.f);
                val.w = fmaxf(fmaf(val.w, __ldg(&ascale[kg + 3]), __ldg(&ashift[kg + 3])), 0.f);
            }
            As[c4 + 0][row] = val.x;
            As[c4 + 1][row] = val.y;
            As[c4 + 2][row] = val.z;
            As[c4 + 3][row] = val.w;
        }
        // load B tile (BK x BN)
#pragma unroll
        for (int t = 0; t < (BK * BN) / (4 * NT); t++) {
            int v = tid + t * NT;
            int kr = v / (BN / 4);
            int c4 = (v % (BN / 4)) << 2;
            *(float4*)&Bs[kr][c4] = *(const float4*)(B + (size_t)(kc + kr) * BN + c4);
        }
        __syncthreads();

#pragma unroll
        for (int k = 0; k < BK; k++) {
            float a[TM], b[TN];
#pragma unroll
            for (int i = 0; i < TM; i += 4)
                *(float4*)&a[i] = *(const float4*)&As[k][ty * TM + i];
#pragma unroll
            for (int j = 0; j < TN; j += 4)
                *(float4*)&b[j] = *(const float4*)&Bs[k][tx * TN + j];
#pragma unroll
            for (int i = 0; i < TM; i++)
#pragma unroll
                for (int j = 0; j < TN; j++)
                    acc[i][j] = fmaf(a[i], b[j], acc[i][j]);
        }
        __syncthreads();
    }

    float bfr[TN];
#pragma unroll
    for (int j = 0; j < TN; j++) bfr[j] = bias ? bias[tx * TN + j] : 0.f;

#pragma unroll
    for (int i = 0; i < TM; i++) {
        int grow = m0 + ty * TM + i;
        if (grow < M) {
            float* cp = C + (size_t)grow * BN + tx * TN;
#pragma unroll
            for (int j = 0; j < TN; j += 4) {
                float4 v;
                v.x = acc[i][j + 0] + bfr[j + 0];
                v.y = acc[i][j + 1] + bfr[j + 1];
                v.z = acc[i][j + 2] + bfr[j + 2];
                v.w = acc[i][j + 3] + bfr[j + 3];
                if (ACCUM) {
                    float4 o = *(float4*)(cp + j);
                    v.x += o.x; v.y += o.y; v.z += o.z; v.w += o.w;
                }
                *(float4*)(cp + j) = v;
            }
        }
    }
}

// ---------------- column stats (sum, sumsq) in double ----------------
__global__ void __launch_bounds__(256) stats_kernel(
    const float* __restrict__ h, long long n, int D,
    double* __restrict__ sum, double* __restrict__ sq)
{
    long long i = (long long)blockIdx.x * 256 + threadIdx.x;
    long long stride = (long long)gridDim.x * 256;
    double ls = 0.0, lq = 0.0;
    for (; i < n; i += stride) {
        float v = h[i];
        ls += v;
        lq += (double)v * v;
    }
    __shared__ double shA[256], shB[256];
    int tid = threadIdx.x;
    shA[tid] = ls; shB[tid] = lq;
    __syncthreads();
    for (int off = 128; off >= D; off >>= 1) {
        if (tid < off) { shA[tid] += shA[tid + off]; shB[tid] += shB[tid + off]; }
        __syncthreads();
    }
    if (tid < D) {
        atomicAdd(&sum[tid], shA[tid]);
        atomicAdd(&sq[tid], shB[tid]);
    }
}

// h2pre = agg2 + r2 + b_rel2 (in place into agg2) fused with column stats (D=32)
__global__ void __launch_bounds__(256) combine_stats_kernel(
    float* __restrict__ agg2, const float* __restrict__ tr,
    const float* __restrict__ b, long long n,
    double* __restrict__ sum, double* __restrict__ sq)
{
    long long i = (long long)blockIdx.x * 256 + threadIdx.x;
    long long stride = (long long)gridDim.x * 256;
    double ls = 0.0, lq = 0.0;
    for (; i < n; i += stride) {
        long long row = i >> 5;
        int c = (int)(i & 31);
        float v = agg2[i] + __ldg(&tr[row * 64 + 32 + c]) + __ldg(&b[c]);
        agg2[i] = v;
        ls += v;
        lq += (double)v * v;
    }
    __shared__ double shA[256], shB[256];
    int tid = threadIdx.x;
    shA[tid] = ls; shB[tid] = lq;
    __syncthreads();
    for (int off = 128; off >= 32; off >>= 1) {
        if (tid < off) { shA[tid] += shA[tid + off]; shB[tid] += shB[tid + off]; }
        __syncthreads();
    }
    if (tid < 32) {
        atomicAdd(&sum[tid], shA[tid]);
        atomicAdd(&sq[tid], shB[tid]);
    }
}

// per-column BN affine coefficients
__global__ void bn_finalize_kernel(
    const double* __restrict__ sum, const double* __restrict__ sq,
    const float* __restrict__ gamma, const float* __restrict__ beta,
    float* __restrict__ scale, float* __restrict__ shift, float invM)
{
    int c = threadIdx.x;
    double mu = sum[c] * (double)invM;
    double var = sq[c] * (double)invM - mu * mu;
    float s = gamma[c] * rsqrtf((float)var + 1e-5f);
    scale[c] = s;
    shift[c] = beta[c] - (float)mu * s;
}

__global__ void __launch_bounds__(256) bn_relu_kernel(
    const float* __restrict__ in, float* __restrict__ out, long long n, int mask,
    const float* __restrict__ scale, const float* __restrict__ shift)
{
    long long i = (long long)blockIdx.x * blockDim.x + threadIdx.x;
    long long stride = (long long)gridDim.x * blockDim.x;
    for (; i < n; i += stride) {
        int c = (int)(i & mask);
        float v = fmaf(in[i], __ldg(&scale[c]), __ldg(&shift[c]));
        out[i] = fmaxf(v, 0.f);
    }
}

static inline int ceil_div_i(int a, int b) { return (a + b - 1) / b; }

// ---------------- launch ----------------
extern "C" void kernel_launch(void* const* d_in, const int* in_sizes, int n_in,
                              void* d_out, int out_size)
{
    const float* x      = (const float*)d_in[0];
    const void*  ei     = d_in[1];
    const float* Wrel1  = (const float*)d_in[2];
    const float* brel1  = (const float*)d_in[3];
    const float* Wroot1 = (const float*)d_in[4];
    const float* gamma1 = (const float*)d_in[5];
    const float* beta1  = (const float*)d_in[6];
    const float* Wrel2  = (const float*)d_in[7];
    const float* brel2  = (const float*)d_in[8];
    const float* Wroot2 = (const float*)d_in[9];
    const float* gamma2 = (const float*)d_in[10];
    const float* beta2  = (const float*)d_in[11];

    const int N = in_sizes[0] / D_IN;
    const int E = in_sizes[1] / 2;

    float *agg1, *h1, *tr, *agg2, *ss, *wcat2;
    double* stats;
    cudaGetSymbolAddress((void**)&agg1, g_agg1);
    cudaGetSymbolAddress((void**)&h1, g_h1);
    cudaGetSymbolAddress((void**)&tr, g_tr);
    cudaGetSymbolAddress((void**)&agg2, g_agg2);
    cudaGetSymbolAddress((void**)&stats, g_stats);
    cudaGetSymbolAddress((void**)&ss, g_ss);
    cudaGetSymbolAddress((void**)&wcat2, g_wcat2);

    // streams/events created on the FIRST call (the correctness run, outside
    // graph capture); reused on every subsequent call. No allocation of device
    // memory is involved.
    static cudaStream_t s2 = nullptr;
    static cudaEvent_t evStart = nullptr, evJoin = nullptr;
    if (!s2) {
        cudaStreamCreateWithFlags(&s2, cudaStreamNonBlocking);
        cudaEventCreateWithFlags(&evStart, cudaEventDisableTiming);
        cudaEventCreateWithFlags(&evJoin, cudaEventDisableTiming);
    }

    // ---- fork ----
    detect_kernel<<<1, 32>>>((const int*)ei, E);
    cudaEventRecord(evStart, 0);
    cudaStreamWaitEvent(s2, evStart, 0);

    // side stream: independent of edge aggregation
    zero4_kernel<<<512, 256, 0, s2>>>(agg2, N * D_OUT / 4);
    zero_d_kernel<<<2, 256, 0, s2>>>(stats, 320);
    prep_w_kernel<<<32, 256, 0, s2>>>(Wrel2, Wroot2, wcat2);
    gemm_kernel<128, 8, false, false><<<ceil_div_i(N, 128), 256, 0, s2>>>(
        x, Wroot1, D_IN, brel1, h1, N, nullptr, nullptr);
    cudaEventRecord(evJoin, s2);

    // main stream: zero + edge scatter in 128-d (L2-atomic bound)
    zero4_kernel<<<2048, 256>>>(agg1, N * D_HID / 4);
    {
        long long t = (long long)E * 32;
        int blocks = (int)((t + 255) / 256);
        scatter_kernel<32><<<blocks, 256>>>(x, D_IN, ei, E, agg1, D_HID);
    }

    // ---- join: h1 += agg1 @ W_rel1 ----
    cudaStreamWaitEvent(0, evJoin, 0);
    gemm_kernel<128, 8, true, false><<<ceil_div_i(N, 128), 256>>>(
        agg1, Wrel1, D_HID, nullptr, h1, N, nullptr, nullptr);

    // BN1 stats on pre-BN h1; normalize+relu fused into gemm2's A-load
    stats_kernel<<<512, 256>>>(h1, (long long)N * D_HID, D_HID, stats, stats + 128);
    bn_finalize_kernel<<<1, 128>>>(stats, stats + 128, gamma1, beta1, ss, ss + 128, 1.0f / (float)N);

    // Layer 2: project FIRST (t = relu(bn(h1))@[W_rel2|W_root2]), then scatter t in 32-d
    gemm_kernel<64, 4, false, true><<<ceil_div_i(N, 128), 256>>>(
        h1, wcat2, D_HID, nullptr, tr, N, ss, ss + 128);
    {
        long long t = (long long)E * 8;
        int blocks = (int)((t + 255) / 256);
        scatter_kernel<8><<<blocks, 256>>>(tr, 64, ei, E, agg2, D_OUT);
    }
    combine_stats_kernel<<<512, 256>>>(agg2, tr, brel2, (long long)N * D_OUT,
                                       stats + 256, stats + 288);
    bn_finalize_kernel<<<1, 32>>>(stats + 256, stats + 288, gamma2, beta2,
                                  ss + 256, ss + 288, 1.0f / (float)N);
    bn_relu_kernel<<<1024, 256>>>(agg2, (float*)d_out, (long long)N * D_OUT, D_OUT - 1,
                                  ss + 256, ss + 288);
}

// round 4
// speedup vs baseline: 1.8808x; 1.2823x over previous
#include <cuda_runtime.h>
#include <cstddef>

#define D_IN  128
#define D_HID 128
#define D_OUT 32
#define NMAX  100000

// ---------------- static device scratch (no runtime allocation) ----------------
__device__ float  g_agg1[(size_t)NMAX * D_HID];
__device__ float  g_h1  [(size_t)NMAX * D_HID];
__device__ float  g_tr  [(size_t)NMAX * 64];      // [t | r2]
__device__ float  g_agg2[(size_t)NMAX * D_OUT];
__device__ double g_stats[320];
__device__ float  g_ss[320];
__device__ float  g_wcat2[128 * 64];
__device__ int    g_is64;

// ---------------- tf32 helpers ----------------
__device__ __forceinline__ unsigned f2tf32(float v) {
    unsigned r;
    asm("cvt.rna.tf32.f32 %0, %1;" : "=r"(r) : "f"(v));
    return r;
}
__device__ __forceinline__ void mma_tf32(float c[4], const unsigned a[4], const unsigned b[2]) {
    asm volatile(
        "mma.sync.aligned.m16n8k8.row.col.f32.tf32.tf32.f32 "
        "{%0,%1,%2,%3}, {%4,%5,%6,%7}, {%8,%9}, {%0,%1,%2,%3};"
        : "+f"(c[0]), "+f"(c[1]), "+f"(c[2]), "+f"(c[3])
        : "r"(a[0]), "r"(a[1]), "r"(a[2]), "r"(a[3]), "r"(b[0]), "r"(b[1]));
}

// ---------------- small utility kernels ----------------
__global__ void zero4_kernel(float* p, int n4) {
    int i = blockIdx.x * blockDim.x + threadIdx.x;
    int stride = gridDim.x * blockDim.x;
    float4 z = make_float4(0.f, 0.f, 0.f, 0.f);
    for (; i < n4; i += stride) ((float4*)p)[i] = z;
}

__global__ void zero_d_kernel(double* p, int n) {
    int i = blockIdx.x * blockDim.x + threadIdx.x;
    if (i < n) p[i] = 0.0;
}

__global__ void detect_kernel(const int* ei, int E) {
    if (threadIdx.x != 0 || blockIdx.x != 0) return;
    int n = 2 * E;
    int allzero = 1;
    for (int k = 1; k < 256 && k < n; k += 2) {
        if (ei[k] != 0) { allzero = 0; break; }
    }
    g_is64 = allzero;
}

__global__ void prep_w_kernel(const float* __restrict__ Wrel2,
                              const float* __restrict__ Wroot2,
                              float* __restrict__ wcat2) {
    int i = blockIdx.x * blockDim.x + threadIdx.x;
    if (i < 128 * 64) {
        int r = i >> 6, c = i & 63;
        wcat2[i] = (c < 32) ? Wrel2[r * 32 + c] : Wroot2[r * 32 + (c - 32)];
    }
}

// ---------------- edge scatter: agg[dst] += feat[src] ----------------
template <int LANES>
__global__ void __launch_bounds__(256) scatter_kernel(
    const float* __restrict__ feat, int featStride,
    const void* __restrict__ eiv, int E,
    float* __restrict__ agg, int aggStride)
{
    int gid = blockIdx.x * 256 + threadIdx.x;
    int e = gid / LANES;
    bool valid = (e < E);
    int lane = threadIdx.x & 31;
    int j = lane & (LANES - 1);
    int grp = lane - j;

    int s = 0, d = 0;
    if (valid && j == 0) {
        if (g_is64) {
            const long long* p = (const long long*)eiv;
            s = (int)p[e];
            d = (int)p[(size_t)E + e];
        } else {
            const int* p = (const int*)eiv;
            s = p[e];
            d = p[E + e];
        }
    }
    s = __shfl_sync(0xffffffffu, s, grp);
    d = __shfl_sync(0xffffffffu, d, grp);
    if (!valid) return;

    const float4 v = *(const float4*)(feat + (size_t)s * featStride + (j << 2));
    float* a = agg + (size_t)d * aggStride + (j << 2);
    asm volatile("red.global.add.v4.f32 [%0], {%1,%2,%3,%4};"
                 :: "l"(a), "f"(v.x), "f"(v.y), "f"(v.z), "f"(v.w)
                 : "memory");
}

// ---------------- tf32 tensor-core GEMM: C = Aa@Ba + Ab@Bb + bias ----------------
// Aa: [M, Ka], Ab: [M, Kb] row-major. Ba/Bb: [Ka/Kb, BN] row-major.
// If BNRELU: A elements pass relu(scale[k]*v + shift[k]) before tf32 conversion.
// Block: 128 rows x BN cols, 256 threads (8 warps = 4 warp-rows x 2 warp-cols).
template <int BN, bool BNRELU>
__global__ void __launch_bounds__(256) gemm_tc_kernel(
    const float* __restrict__ Aa, const float* __restrict__ Ba, int Ka,
    const float* __restrict__ Ab, const float* __restrict__ Bb, int Kb,
    const float* __restrict__ bias, float* __restrict__ C, int M,
    const float* __restrict__ ascale, const float* __restrict__ ashift)
{
    constexpr int BM = 128, BK = 32;
    constexpr int WN = BN / 2;          // warp tile cols
    constexpr int NT = WN / 8;          // n-subtiles per warp
    constexpr int APAD = 4, BPAD = 8;
    __shared__ unsigned As[BM][BK + APAD];   // [m][k], tf32 bits
    __shared__ unsigned Bs[BK][BN + BPAD];   // [k][n], tf32 bits

    const int tid = threadIdx.x;
    const int lane = tid & 31;
    const int wid = tid >> 5;
    const int warp_m = wid & 3;          // 0..3 -> rows
    const int warp_n = wid >> 2;         // 0..1 -> cols
    const int m0 = blockIdx.x * BM;
    const int tg = lane & 3;             // threadID in group
    const int gi = lane >> 2;            // group id (0..7)

    float acc[2][NT][4];
#pragma unroll
    for (int mt = 0; mt < 2; mt++)
#pragma unroll
        for (int nt = 0; nt < NT; nt++)
#pragma unroll
            for (int r = 0; r < 4; r++) acc[mt][nt][r] = 0.f;

    const int K = Ka + Kb;
    for (int kc = 0; kc < K; kc += BK) {
        const float* A; const float* B; int lda, kloc;
        if (kc < Ka) { A = Aa; B = Ba; lda = Ka; kloc = kc; }
        else         { A = Ab; B = Bb; lda = Kb; kloc = kc - Ka; }

        // ---- stage A tile (BM x BK) as tf32 into As[m][k] ----
#pragma unroll
        for (int t = 0; t < (BM * BK) / (4 * 256); t++) {   // 4 float4 per thread
            int v = tid + t * 256;
            int row = v >> 3;                 // BK/4 = 8 float4 per row
            int c4 = (v & 7) << 2;
            float4 val = make_float4(0.f, 0.f, 0.f, 0.f);
            if (m0 + row < M)
                val = *(const float4*)(A + (size_t)(m0 + row) * lda + kloc + c4);
            if (BNRELU) {
                int kg = kc + c4;
                val.x = fmaxf(fmaf(val.x, __ldg(&ascale[kg + 0]), __ldg(&ashift[kg + 0])), 0.f);
                val.y = fmaxf(fmaf(val.y, __ldg(&ascale[kg + 1]), __ldg(&ashift[kg + 1])), 0.f);
                val.z = fmaxf(fmaf(val.z, __ldg(&ascale[kg + 2]), __ldg(&ashift[kg + 2])), 0.f);
                val.w = fmaxf(fmaf(val.w, __ldg(&ascale[kg + 3]), __ldg(&ashift[kg + 3])), 0.f);
            }
            uint4 u;
            u.x = f2tf32(val.x); u.y = f2tf32(val.y);
            u.z = f2tf32(val.z); u.w = f2tf32(val.w);
            *(uint4*)&As[row][c4] = u;
        }
        // ---- stage B tile (BK x BN) as tf32 into Bs[k][n] ----
#pragma unroll
        for (int t = 0; t < (BK * BN) / (4 * 256); t++) {
            int v = tid + t * 256;
            int kr = v / (BN / 4);
            int c4 = (v % (BN / 4)) << 2;
            float4 val = *(const float4*)(B + (size_t)(kloc + kr) * BN + c4);
            uint4 u;
            u.x = f2tf32(val.x); u.y = f2tf32(val.y);
            u.z = f2tf32(val.z); u.w = f2tf32(val.w);
            *(uint4*)&Bs[kr][c4] = u;
        }
        __syncthreads();

        // ---- compute: 4 k8-steps ----
#pragma unroll
        for (int ks = 0; ks < BK / 8; ks++) {
            int k8 = ks * 8;
            unsigned a[2][4];
#pragma unroll
            for (int mt = 0; mt < 2; mt++) {
                int rb = warp_m * 32 + mt * 16;
                a[mt][0] = As[rb + gi][k8 + tg];
                a[mt][1] = As[rb + 8 + gi][k8 + tg];
                a[mt][2] = As[rb + gi][k8 + 4 + tg];
                a[mt][3] = As[rb + 8 + gi][k8 + 4 + tg];
            }
            unsigned b[NT][2];
#pragma unroll
            for (int nt = 0; nt < NT; nt++) {
                int col = warp_n * WN + nt * 8 + gi;
                b[nt][0] = Bs[k8 + tg][col];
                b[nt][1] = Bs[k8 + 4 + tg][col];
            }
#pragma unroll
            for (int mt = 0; mt < 2; mt++)
#pragma unroll
                for (int nt = 0; nt < NT; nt++)
                    mma_tf32(acc[mt][nt], a[mt], b[nt]);
        }
        __syncthreads();
    }

    // ---- epilogue: bias + store ----
#pragma unroll
    for (int mt = 0; mt < 2; mt++) {
        int r0 = m0 + warp_m * 32 + mt * 16 + gi;
        int r1 = r0 + 8;
#pragma unroll
        for (int nt = 0; nt < NT; nt++) {
            int col = warp_n * WN + nt * 8 + tg * 2;
            float bx = bias ? __ldg(&bias[col]) : 0.f;
            float by = bias ? __ldg(&bias[col + 1]) : 0.f;
            if (r0 < M) {
                float2 v0 = make_float2(acc[mt][nt][0] + bx, acc[mt][nt][1] + by);
                *(float2*)(C + (size_t)r0 * BN + col) = v0;
            }
            if (r1 < M) {
                float2 v1 = make_float2(acc[mt][nt][2] + bx, acc[mt][nt][3] + by);
                *(float2*)(C + (size_t)r1 * BN + col) = v1;
            }
        }
    }
}

// ---------------- column stats (sum, sumsq) in double ----------------
__global__ void __launch_bounds__(256) stats_kernel(
    const float* __restrict__ h, long long n, int D,
    double* __restrict__ sum, double* __restrict__ sq)
{
    long long i = (long long)blockIdx.x * 256 + threadIdx.x;
    long long stride = (long long)gridDim.x * 256;
    double ls = 0.0, lq = 0.0;
    for (; i < n; i += stride) {
        float v = h[i];
        ls += v;
        lq += (double)v * v;
    }
    __shared__ double shA[256], shB[256];
    int tid = threadIdx.x;
    shA[tid] = ls; shB[tid] = lq;
    __syncthreads();
    for (int off = 128; off >= D; off >>= 1) {
        if (tid < off) { shA[tid] += shA[tid + off]; shB[tid] += shB[tid + off]; }
        __syncthreads();
    }
    if (tid < D) {
        atomicAdd(&sum[tid], shA[tid]);
        atomicAdd(&sq[tid], shB[tid]);
    }
}

__global__ void __launch_bounds__(256) combine_stats_kernel(
    float* __restrict__ agg2, const float* __restrict__ tr,
    const float* __restrict__ b, long long n,
    double* __restrict__ sum, double* __restrict__ sq)
{
    long long i = (long long)blockIdx.x * 256 + threadIdx.x;
    long long stride = (long long)gridDim.x * 256;
    double ls = 0.0, lq = 0.0;
    for (; i < n; i += stride) {
        long long row = i >> 5;
        int c = (int)(i & 31);
        float v = agg2[i] + __ldg(&tr[row * 64 + 32 + c]) + __ldg(&b[c]);
        agg2[i] = v;
        ls += v;
        lq += (double)v * v;
    }
    __shared__ double shA[256], shB[256];
    int tid = threadIdx.x;
    shA[tid] = ls; shB[tid] = lq;
    __syncthreads();
    for (int off = 128; off >= 32; off >>= 1) {
        if (tid < off) { shA[tid] += shA[tid + off]; shB[tid] += shB[tid + off]; }
        __syncthreads();
    }
    if (tid < 32) {
        atomicAdd(&sum[tid], shA[tid]);
        atomicAdd(&sq[tid], shB[tid]);
    }
}

__global__ void bn_finalize_kernel(
    const double* __restrict__ sum, const double* __restrict__ sq,
    const float* __restrict__ gamma, const float* __restrict__ beta,
    float* __restrict__ scale, float* __restrict__ shift, float invM)
{
    int c = threadIdx.x;
    double mu = sum[c] * (double)invM;
    double var = sq[c] * (double)invM - mu * mu;
    float s = gamma[c] * rsqrtf((float)var + 1e-5f);
    scale[c] = s;
    shift[c] = beta[c] - (float)mu * s;
}

__global__ void __launch_bounds__(256) bn_relu_kernel(
    const float* __restrict__ in, float* __restrict__ out, long long n, int mask,
    const float* __restrict__ scale, const float* __restrict__ shift)
{
    long long i = (long long)blockIdx.x * blockDim.x + threadIdx.x;
    long long stride = (long long)gridDim.x * blockDim.x;
    for (; i < n; i += stride) {
        int c = (int)(i & mask);
        float v = fmaf(in[i], __ldg(&scale[c]), __ldg(&shift[c]));
        out[i] = fmaxf(v, 0.f);
    }
}

static inline int ceil_div_i(int a, int b) { return (a + b - 1) / b; }

// ---------------- launch ----------------
extern "C" void kernel_launch(void* const* d_in, const int* in_sizes, int n_in,
                              void* d_out, int out_size)
{
    const float* x      = (const float*)d_in[0];
    const void*  ei     = d_in[1];
    const float* Wrel1  = (const float*)d_in[2];
    const float* brel1  = (const float*)d_in[3];
    const float* Wroot1 = (const float*)d_in[4];
    const float* gamma1 = (const float*)d_in[5];
    const float* beta1  = (const float*)d_in[6];
    const float* Wrel2  = (const float*)d_in[7];
    const float* brel2  = (const float*)d_in[8];
    const float* Wroot2 = (const float*)d_in[9];
    const float* gamma2 = (const float*)d_in[10];
    const float* beta2  = (const float*)d_in[11];

    const int N = in_sizes[0] / D_IN;
    const int E = in_sizes[1] / 2;

    float *agg1, *h1, *tr, *agg2, *ss, *wcat2;
    double* stats;
    cudaGetSymbolAddress((void**)&agg1, g_agg1);
    cudaGetSymbolAddress((void**)&h1, g_h1);
    cudaGetSymbolAddress((void**)&tr, g_tr);
    cudaGetSymbolAddress((void**)&agg2, g_agg2);
    cudaGetSymbolAddress((void**)&stats, g_stats);
    cudaGetSymbolAddress((void**)&ss, g_ss);
    cudaGetSymbolAddress((void**)&wcat2, g_wcat2);

    // launches 0..4 (small), so scatter1 is launch index 5 -> ncu -s 5 captures it
    detect_kernel<<<1, 32>>>((const int*)ei, E);
    zero_d_kernel<<<2, 256>>>(stats, 320);
    prep_w_kernel<<<32, 256>>>(Wrel2, Wroot2, wcat2);
    zero4_kernel<<<512, 256>>>(agg2, N * D_OUT / 4);
    zero4_kernel<<<2048, 256>>>(agg1, N * D_HID / 4);

    // Layer 1 aggregation (launch #5)
    {
        long long t = (long long)E * 32;
        int blocks = (int)((t + 255) / 256);
        scatter_kernel<32><<<blocks, 256>>>(x, D_IN, ei, E, agg1, D_HID);
    }
    // h1 = agg1 @ W_rel1 + x @ W_root1 + b_rel1  (tf32 tensor cores)
    gemm_tc_kernel<128, false><<<ceil_div_i(N, 128), 256>>>(
        agg1, Wrel1, D_HID, x, Wroot1, D_IN, brel1, h1, N, nullptr, nullptr);

    // BN1 stats; normalize+relu fused into gemm2's A-load
    stats_kernel<<<512, 256>>>(h1, (long long)N * D_HID, D_HID, stats, stats + 128);
    bn_finalize_kernel<<<1, 128>>>(stats, stats + 128, gamma1, beta1, ss, ss + 128, 1.0f / (float)N);

    // Layer 2: project first, then scatter in 32-d
    gemm_tc_kernel<64, true><<<ceil_div_i(N, 128), 256>>>(
        h1, wcat2, D_HID, nullptr, nullptr, 0, nullptr, tr, N, ss, ss + 128);
    {
        long long t = (long long)E * 8;
        int blocks = (int)((t + 255) / 256);
        scatter_kernel<8><<<blocks, 256>>>(tr, 64, ei, E, agg2, D_OUT);
    }
    combine_stats_kernel<<<512, 256>>>(agg2, tr, brel2, (long long)N * D_OUT,
                                       stats + 256, stats + 288);
    bn_finalize_kernel<<<1, 32>>>(stats + 256, stats + 288, gamma2, beta2,
                                  ss + 256, ss + 288, 1.0f / (float)N);
    bn_relu_kernel<<<1024, 256>>>(agg2, (float*)d_out, (long long)N * D_OUT, D_OUT - 1,
                                  ss + 256, ss + 288);
}

// round 5
// speedup vs baseline: 2.8147x; 1.4966x over previous
#include <cuda_runtime.h>
#include <cstddef>

#define D_IN  128
#define D_HID 128
#define D_OUT 32
#define NMAX  100000
#define EMAX  1601000
#define SCHUNK 1024

// ---------------- static device scratch (no runtime allocation) ----------------
__device__ float  g_agg1[(size_t)NMAX * D_HID];
__device__ float  g_h1  [(size_t)NMAX * D_HID];
__device__ float  g_tr  [(size_t)NMAX * 64];      // [t | r2]
__device__ float  g_agg2[(size_t)NMAX * D_OUT];
__device__ double g_stats[320];
__device__ float  g_ss[320];
__device__ float  g_wcat2[128 * 64];
__device__ int    g_off[NMAX + 1];
__device__ int    g_sums[128];                    // chunk sums for scan
__device__ int    g_csrc[EMAX];
__device__ int    g_is64;

// ---------------- tf32 helpers ----------------
__device__ __forceinline__ unsigned f2tf32(float v) {
    unsigned r;
    asm("cvt.rna.tf32.f32 %0, %1;" : "=r"(r) : "f"(v));
    return r;
}
__device__ __forceinline__ void mma_tf32(float c[4], const unsigned a[4], const unsigned b[2]) {
    asm volatile(
        "mma.sync.aligned.m16n8k8.row.col.f32.tf32.tf32.f32 "
        "{%0,%1,%2,%3}, {%4,%5,%6,%7}, {%8,%9}, {%0,%1,%2,%3};"
        : "+f"(c[0]), "+f"(c[1]), "+f"(c[2]), "+f"(c[3])
        : "r"(a[0]), "r"(a[1]), "r"(a[2]), "r"(a[3]), "r"(b[0]), "r"(b[1]));
}

// ---------------- CSR construction ----------------
// launch #0: zero deg (stored in g_off[0..N-1]) + detect int64 vs int32
__global__ void zero_detect_kernel(const int* ei, int E, int* deg, int N) {
    int i = blockIdx.x * blockDim.x + threadIdx.x;
    int stride = gridDim.x * blockDim.x;
    for (; i <= N; i += stride) deg[i] = 0;
    if (blockIdx.x == 0 && threadIdx.x == 0) {
        int n = 2 * E;
        int allzero = 1;
        for (int k = 1; k < 256 && k < n; k += 2) {
            if (ei[k] != 0) { allzero = 0; break; }
        }
        g_is64 = allzero;
    }
}

__device__ __forceinline__ void load_edge(const void* eiv, int E, int e, int& s, int& d) {
    if (g_is64) {
        const long long* p = (const long long*)eiv;
        s = (int)p[e];
        d = (int)p[(size_t)E + e];
    } else {
        const int* p = (const int*)eiv;
        s = p[e];
        d = p[E + e];
    }
}

// launch #1: histogram of destination degrees
__global__ void __launch_bounds__(256) hist_kernel(const void* eiv, int E, int* deg) {
    int e = blockIdx.x * 256 + threadIdx.x;
    int stride = gridDim.x * 256;
    for (; e < E; e += stride) {
        int s, d;
        load_edge(eiv, E, e, s, d);
        atomicAdd(&deg[d], 1);
    }
}

// launch #2: per-chunk inclusive scan; deg read from off[i], result to off[i+1]; chunk sums out
__global__ void __launch_bounds__(SCHUNK) scan_chunk_kernel(int* off, int N, int* sums) {
    __shared__ int sh[SCHUNK];
    int b = blockIdx.x;
    int i = b * SCHUNK + threadIdx.x;
    int v = (i < N) ? off[i] : 0;
    sh[threadIdx.x] = v;
    __syncthreads();
#pragma unroll
    for (int o = 1; o < SCHUNK; o <<= 1) {
        int t = (threadIdx.x >= (unsigned)o) ? sh[threadIdx.x - o] : 0;
        __syncthreads();
        sh[threadIdx.x] += t;
        __syncthreads();
    }
    if (i < N) off[i + 1] = sh[threadIdx.x];   // raw inclusive (per chunk)
    if (threadIdx.x == SCHUNK - 1) sums[b] = sh[threadIdx.x];
}

// launch #3: add chunk bases (thread 0 of each block sums prior chunk totals), set off[0]=0
__global__ void __launch_bounds__(SCHUNK) scan_add_kernel(int* off, int N, const int* sums) {
    __shared__ int base_sh;
    int b = blockIdx.x;
    if (threadIdx.x == 0) {
        int base = 0;
        for (int k = 0; k < b; k++) base += sums[k];
        base_sh = base;
        if (b == 0) off[0] = 0;
    }
    __syncthreads();
    int i = b * SCHUNK + threadIdx.x;
    if (i < N) off[i + 1] += base_sh;
}

// launch #4: bucket fill. atomicAdd on off[d] itself (cursor). After this kernel,
// off[d] = END of bucket d; begin(d) = (d==0) ? 0 : off[d-1].
__global__ void __launch_bounds__(256) fill_kernel(const void* eiv, int E, int* off, int* csrc) {
    int e = blockIdx.x * 256 + threadIdx.x;
    int stride = gridDim.x * 256;
    for (; e < E; e += stride) {
        int s, d;
        load_edge(eiv, E, e, s, d);
        int pos = atomicAdd(&off[d], 1);
        csrc[pos] = s;
    }
}

// ---------------- CSR gather: out[w] = sum_{s in nbrs(w)} feat[s] ----------------
// F4 float4-lanes per row. off is post-fill (off[w]=end, off[w-1]=begin).
template <int F4, int FSTRIDE, int OSTRIDE>
__global__ void __launch_bounds__(256) gather_kernel(
    const float* __restrict__ feat, const int* __restrict__ off,
    const int* __restrict__ csrc, float* __restrict__ out, int N)
{
    int gid = blockIdx.x * 256 + threadIdx.x;
    int w = gid / F4;
    int j = gid % F4;
    if (w >= N) return;
    int end = __ldg(&off[w]);
    int beg = (w == 0) ? 0 : __ldg(&off[w - 1]);

    float4 acc = make_float4(0.f, 0.f, 0.f, 0.f);
    int k = beg;
    for (; k + 2 <= end; k += 2) {
        int s0 = __ldg(&csrc[k]);
        int s1 = __ldg(&csrc[k + 1]);
        float4 v0 = *(const float4*)(feat + (size_t)s0 * FSTRIDE + (j << 2));
        float4 v1 = *(const float4*)(feat + (size_t)s1 * FSTRIDE + (j << 2));
        acc.x += v0.x + v1.x;
        acc.y += v0.y + v1.y;
        acc.z += v0.z + v1.z;
        acc.w += v0.w + v1.w;
    }
    if (k < end) {
        int s0 = __ldg(&csrc[k]);
        float4 v0 = *(const float4*)(feat + (size_t)s0 * FSTRIDE + (j << 2));
        acc.x += v0.x; acc.y += v0.y; acc.z += v0.z; acc.w += v0.w;
    }
    *(float4*)(out + (size_t)w * OSTRIDE + (j << 2)) = acc;
}

// ---------------- misc small kernels ----------------
__global__ void zero_d_kernel(double* p, int n) {
    int i = blockIdx.x * blockDim.x + threadIdx.x;
    if (i < n) p[i] = 0.0;
}

__global__ void prep_w_kernel(const float* __restrict__ Wrel2,
                              const float* __restrict__ Wroot2,
                              float* __restrict__ wcat2) {
    int i = blockIdx.x * blockDim.x + threadIdx.x;
    if (i < 128 * 64) {
        int r = i >> 6, c = i & 63;
        wcat2[i] = (c < 32) ? Wrel2[r * 32 + c] : Wroot2[r * 32 + (c - 32)];
    }
}

// ---------------- tf32 tensor-core GEMM: C = Aa@Ba + Ab@Bb + bias ----------------
template <int BN, bool BNRELU>
__global__ void __launch_bounds__(256) gemm_tc_kernel(
    const float* __restrict__ Aa, const float* __restrict__ Ba, int Ka,
    const float* __restrict__ Ab, const float* __restrict__ Bb, int Kb,
    const float* __restrict__ bias, float* __restrict__ C, int M,
    const float* __restrict__ ascale, const float* __restrict__ ashift)
{
    constexpr int BM = 128, BK = 32;
    constexpr int WN = BN / 2;
    constexpr int NT = WN / 8;
    constexpr int APAD = 4, BPAD = 8;
    __shared__ unsigned As[BM][BK + APAD];
    __shared__ unsigned Bs[BK][BN + BPAD];

    const int tid = threadIdx.x;
    const int lane = tid & 31;
    const int wid = tid >> 5;
    const int warp_m = wid & 3;
    const int warp_n = wid >> 2;
    const int m0 = blockIdx.x * BM;
    const int tg = lane & 3;
    const int gi = lane >> 2;

    float acc[2][NT][4];
#pragma unroll
    for (int mt = 0; mt < 2; mt++)
#pragma unroll
        for (int nt = 0; nt < NT; nt++)
#pragma unroll
            for (int r = 0; r < 4; r++) acc[mt][nt][r] = 0.f;

    const int K = Ka + Kb;
    for (int kc = 0; kc < K; kc += BK) {
        const float* A; const float* B; int lda, kloc;
        if (kc < Ka) { A = Aa; B = Ba; lda = Ka; kloc = kc; }
        else         { A = Ab; B = Bb; lda = Kb; kloc = kc - Ka; }

#pragma unroll
        for (int t = 0; t < (BM * BK) / (4 * 256); t++) {
            int v = tid + t * 256;
            int row = v >> 3;
            int c4 = (v & 7) << 2;
            float4 val = make_float4(0.f, 0.f, 0.f, 0.f);
            if (m0 + row < M)
                val = *(const float4*)(A + (size_t)(m0 + row) * lda + kloc + c4);
            if (BNRELU) {
                int kg = kc + c4;
                val.x = fmaxf(fmaf(val.x, __ldg(&ascale[kg + 0]), __ldg(&ashift[kg + 0])), 0.f);
                val.y = fmaxf(fmaf(val.y, __ldg(&ascale[kg + 1]), __ldg(&ashift[kg + 1])), 0.f);
                val.z = fmaxf(fmaf(val.z, __ldg(&ascale[kg + 2]), __ldg(&ashift[kg + 2])), 0.f);
                val.w = fmaxf(fmaf(val.w, __ldg(&ascale[kg + 3]), __ldg(&ashift[kg + 3])), 0.f);
            }
            uint4 u;
            u.x = f2tf32(val.x); u.y = f2tf32(val.y);
            u.z = f2tf32(val.z); u.w = f2tf32(val.w);
            *(uint4*)&As[row][c4] = u;
        }
#pragma unroll
        for (int t = 0; t < (BK * BN) / (4 * 256); t++) {
            int v = tid + t * 256;
            int kr = v / (BN / 4);
            int c4 = (v % (BN / 4)) << 2;
            float4 val = *(const float4*)(B + (size_t)(kloc + kr) * BN + c4);
            uint4 u;
            u.x = f2tf32(val.x); u.y = f2tf32(val.y);
            u.z = f2tf32(val.z); u.w = f2tf32(val.w);
            *(uint4*)&Bs[kr][c4] = u;
        }
        __syncthreads();

#pragma unroll
        for (int ks = 0; ks < BK / 8; ks++) {
            int k8 = ks * 8;
            unsigned a[2][4];
#pragma unroll
            for (int mt = 0; mt < 2; mt++) {
                int rb = warp_m * 32 + mt * 16;
                a[mt][0] = As[rb + gi][k8 + tg];
                a[mt][1] = As[rb + 8 + gi][k8 + tg];
                a[mt][2] = As[rb + gi][k8 + 4 + tg];
                a[mt][3] = As[rb + 8 + gi][k8 + 4 + tg];
            }
            unsigned b[NT][2];
#pragma unroll
            for (int nt = 0; nt < NT; nt++) {
                int col = warp_n * WN + nt * 8 + gi;
                b[nt][0] = Bs[k8 + tg][col];
                b[nt][1] = Bs[k8 + 4 + tg][col];
            }
#pragma unroll
            for (int mt = 0; mt < 2; mt++)
#pragma unroll
                for (int nt = 0; nt < NT; nt++)
                    mma_tf32(acc[mt][nt], a[mt], b[nt]);
        }
        __syncthreads();
    }

#pragma unroll
    for (int mt = 0; mt < 2; mt++) {
        int r0 = m0 + warp_m * 32 + mt * 16 + gi;
        int r1 = r0 + 8;
#pragma unroll
        for (int nt = 0; nt < NT; nt++) {
            int col = warp_n * WN + nt * 8 + tg * 2;
            float bx = bias ? __ldg(&bias[col]) : 0.f;
            float by = bias ? __ldg(&bias[col + 1]) : 0.f;
            if (r0 < M) {
                float2 v0 = make_float2(acc[mt][nt][0] + bx, acc[mt][nt][1] + by);
                *(float2*)(C + (size_t)r0 * BN + col) = v0;
            }
            if (r1 < M) {
                float2 v1 = make_float2(acc[mt][nt][2] + bx, acc[mt][nt][3] + by);
                *(float2*)(C + (size_t)r1 * BN + col) = v1;
            }
        }
    }
}

// ---------------- column stats (sum, sumsq) in double ----------------
__global__ void __launch_bounds__(256) stats_kernel(
    const float* __restrict__ h, long long n, int D,
    double* __restrict__ sum, double* __restrict__ sq)
{
    long long i = (long long)blockIdx.x * 256 + threadIdx.x;
    long long stride = (long long)gridDim.x * 256;
    double ls = 0.0, lq = 0.0;
    for (; i < n; i += stride) {
        float v = h[i];
        ls += v;
        lq += (double)v * v;
    }
    __shared__ double shA[256], shB[256];
    int tid = threadIdx.x;
    shA[tid] = ls; shB[tid] = lq;
    __syncthreads();
    for (int off = 128; off >= D; off >>= 1) {
        if (tid < off) { shA[tid] += shA[tid + off]; shB[tid] += shB[tid + off]; }
        __syncthreads();
    }
    if (tid < D) {
        atomicAdd(&sum[tid], shA[tid]);
        atomicAdd(&sq[tid], shB[tid]);
    }
}

__global__ void __launch_bounds__(256) combine_stats_kernel(
    float* __restrict__ agg2, const float* __restrict__ tr,
    const float* __restrict__ b, long long n,
    double* __restrict__ sum, double* __restrict__ sq)
{
    long long i = (long long)blockIdx.x * 256 + threadIdx.x;
    long long stride = (long long)gridDim.x * 256;
    double ls = 0.0, lq = 0.0;
    for (; i < n; i += stride) {
        long long row = i >> 5;
        int c = (int)(i & 31);
        float v = agg2[i] + __ldg(&tr[row * 64 + 32 + c]) + __ldg(&b[c]);
        agg2[i] = v;
        ls += v;
        lq += (double)v * v;
    }
    __shared__ double shA[256], shB[256];
    int tid = threadIdx.x;
    shA[tid] = ls; shB[tid] = lq;
    __syncthreads();
    for (int off = 128; off >= 32; off >>= 1) {
        if (tid < off) { shA[tid] += shA[tid + off]; shB[tid] += shB[tid + off]; }
        __syncthreads();
    }
    if (tid < 32) {
        atomicAdd(&sum[tid], shA[tid]);
        atomicAdd(&sq[tid], shB[tid]);
    }
}

__global__ void bn_finalize_kernel(
    const double* __restrict__ sum, const double* __restrict__ sq,
    const float* __restrict__ gamma, const float* __restrict__ beta,
    float* __restrict__ scale, float* __restrict__ shift, float invM)
{
    int c = threadIdx.x;
    double mu = sum[c] * (double)invM;
    double var = sq[c] * (double)invM - mu * mu;
    float s = gamma[c] * rsqrtf((float)var + 1e-5f);
    scale[c] = s;
    shift[c] = beta[c] - (float)mu * s;
}

__global__ void __launch_bounds__(256) bn_relu_kernel(
    const float* __restrict__ in, float* __restrict__ out, long long n, int mask,
    const float* __restrict__ scale, const float* __restrict__ shift)
{
    long long i = (long long)blockIdx.x * blockDim.x + threadIdx.x;
    long long stride = (long long)gridDim.x * blockDim.x;
    for (; i < n; i += stride) {
        int c = (int)(i & mask);
        float v = fmaf(in[i], __ldg(&scale[c]), __ldg(&shift[c]));
        out[i] = fmaxf(v, 0.f);
    }
}

static inline int ceil_div_i(int a, int b) { return (a + b - 1) / b; }

// ---------------- launch ----------------
extern "C" void kernel_launch(void* const* d_in, const int* in_sizes, int n_in,
                              void* d_out, int out_size)
{
    const float* x      = (const float*)d_in[0];
    const void*  ei     = d_in[1];
    const float* Wrel1  = (const float*)d_in[2];
    const float* brel1  = (const float*)d_in[3];
    const float* Wroot1 = (const float*)d_in[4];
    const float* gamma1 = (const float*)d_in[5];
    const float* beta1  = (const float*)d_in[6];
    const float* Wrel2  = (const float*)d_in[7];
    const float* brel2  = (const float*)d_in[8];
    const float* Wroot2 = (const float*)d_in[9];
    const float* gamma2 = (const float*)d_in[10];
    const float* beta2  = (const float*)d_in[11];

    const int N = in_sizes[0] / D_IN;
    const int E = in_sizes[1] / 2;

    float *agg1, *h1, *tr, *agg2, *ss, *wcat2;
    double* stats;
    int *off, *sums, *csrc;
    cudaGetSymbolAddress((void**)&agg1, g_agg1);
    cudaGetSymbolAddress((void**)&h1, g_h1);
    cudaGetSymbolAddress((void**)&tr, g_tr);
    cudaGetSymbolAddress((void**)&agg2, g_agg2);
    cudaGetSymbolAddress((void**)&stats, g_stats);
    cudaGetSymbolAddress((void**)&ss, g_ss);
    cudaGetSymbolAddress((void**)&wcat2, g_wcat2);
    cudaGetSymbolAddress((void**)&off, g_off);
    cudaGetSymbolAddress((void**)&sums, g_sums);
    cudaGetSymbolAddress((void**)&csrc, g_csrc);

    const int nchunks = ceil_div_i(N, SCHUNK);
    const int eblocks = ceil_div_i(E, 256);

    // ---- CSR build (launches 0..4) ----
    zero_detect_kernel<<<128, 256>>>((const int*)ei, E, off, N);      // #0
    hist_kernel<<<eblocks, 256>>>(ei, E, off);                        // #1
    scan_chunk_kernel<<<nchunks, SCHUNK>>>(off, N, sums);             // #2
    scan_add_kernel<<<nchunks, SCHUNK>>>(off, N, sums);               // #3
    fill_kernel<<<eblocks, 256>>>(ei, E, off, csrc);                  // #4

    // ---- layer 1: gather (launch #5, profiled by ncu -s 5) ----
    gather_kernel<32, D_IN, D_HID><<<ceil_div_i(N * 32, 256), 256>>>(x, off, csrc, agg1, N);
    // h1 = agg1 @ W_rel1 + x @ W_root1 + b_rel1  (tf32 tensor cores)
    gemm_tc_kernel<128, false><<<ceil_div_i(N, 128), 256>>>(
        agg1, Wrel1, D_HID, x, Wroot1, D_IN, brel1, h1, N, nullptr, nullptr);

    zero_d_kernel<<<2, 256>>>(stats, 320);
    prep_w_kernel<<<32, 256>>>(Wrel2, Wroot2, wcat2);

    // BN1 stats; normalize+relu fused into gemm2's A-load
    stats_kernel<<<512, 256>>>(h1, (long long)N * D_HID, D_HID, stats, stats + 128);
    bn_finalize_kernel<<<1, 128>>>(stats, stats + 128, gamma1, beta1, ss, ss + 128, 1.0f / (float)N);

    // ---- layer 2: project first, then gather in 32-d ----
    gemm_tc_kernel<64, true><<<ceil_div_i(N, 128), 256>>>(
        h1, wcat2, D_HID, nullptr, nullptr, 0, nullptr, tr, N, ss, ss + 128);
    gather_kernel<8, 64, D_OUT><<<ceil_div_i(N * 8, 256), 256>>>(tr, off, csrc, agg2, N);

    combine_stats_kernel<<<512, 256>>>(agg2, tr, brel2, (long long)N * D_OUT,
                                       stats + 256, stats + 288);
    bn_finalize_kernel<<<1, 32>>>(stats + 256, stats + 288, gamma2, beta2,
                                  ss + 256, ss + 288, 1.0f / (float)N);
    bn_relu_kernel<<<1024, 256>>>(agg2, (float*)d_out, (long long)N * D_OUT, D_OUT - 1,
                                  ss + 256, ss + 288);
}

// round 6
// speedup vs baseline: 3.7219x; 1.3223x over previous
#include <cuda_runtime.h>
#include <cuda_fp16.h>
#include <cstddef>

#define D_IN  128
#define D_HID 128
#define D_OUT 32
#define NMAX  100000
#define EMAX  1601000
#define SCHUNK 1024

// ---------------- static device scratch (no runtime allocation) ----------------
__device__ __half g_x16 [(size_t)NMAX * D_IN];    // fp16 copy of x
__device__ __half g_agg1h[(size_t)NMAX * D_HID];  // gathered x (fp16)
__device__ float  g_h1  [(size_t)NMAX * D_HID];   // pre-BN h1
__device__ float  g_tr  [(size_t)NMAX * 64];      // cols 32..63 = r2 (fp32)
__device__ __half g_t16 [(size_t)NMAX * 32];      // t = relu(bn(h1))@W_rel2 (fp16)
__device__ float  g_agg2[(size_t)NMAX * D_OUT];
__device__ double g_stats[320];
__device__ float  g_ss[320];
__device__ float  g_wcat2[128 * 64];
__device__ int    g_off[NMAX + 1];
__device__ int    g_sums[128];
__device__ int    g_csrc[EMAX];
__device__ int    g_is64;

// ---------------- tf32 helpers ----------------
__device__ __forceinline__ unsigned f2tf32(float v) {
    unsigned r;
    asm("cvt.rna.tf32.f32 %0, %1;" : "=r"(r) : "f"(v));
    return r;
}
__device__ __forceinline__ void mma_tf32(float c[4], const unsigned a[4], const unsigned b[2]) {
    asm volatile(
        "mma.sync.aligned.m16n8k8.row.col.f32.tf32.tf32.f32 "
        "{%0,%1,%2,%3}, {%4,%5,%6,%7}, {%8,%9}, {%0,%1,%2,%3};"
        : "+f"(c[0]), "+f"(c[1]), "+f"(c[2]), "+f"(c[3])
        : "r"(a[0]), "r"(a[1]), "r"(a[2]), "r"(a[3]), "r"(b[0]), "r"(b[1]));
}

// ---------------- launch #0: zero off/stats + detect dtype + x -> fp16 ----------------
__global__ void __launch_bounds__(256) init_kernel(
    const int* ei, int E, int* off, int N, double* stats,
    const float* __restrict__ x, __half* __restrict__ x16, long long nh2)
{
    long long i = (long long)blockIdx.x * 256 + threadIdx.x;
    long long stride = (long long)gridDim.x * 256;
    for (long long t = i; t <= N; t += stride) off[t] = 0;
    for (long long t = i; t < 320; t += stride) stats[t] = 0.0;
    const float2* xf2 = (const float2*)x;
    __half2* xh2 = (__half2*)x16;
    for (long long t = i; t < nh2; t += stride)
        xh2[t] = __float22half2_rn(xf2[t]);
    if (blockIdx.x == 0 && threadIdx.x == 0) {
        int n = 2 * E;
        int allzero = 1;
        for (int k = 1; k < 256 && k < n; k += 2) {
            if (ei[k] != 0) { allzero = 0; break; }
        }
        g_is64 = allzero;
    }
}

__device__ __forceinline__ void load_edge(const void* eiv, int E, int e, int& s, int& d) {
    if (g_is64) {
        const long long* p = (const long long*)eiv;
        s = (int)p[e];
        d = (int)p[(size_t)E + e];
    } else {
        const int* p = (const int*)eiv;
        s = p[e];
        d = p[E + e];
    }
}

// ---------------- CSR build ----------------
__global__ void __launch_bounds__(256) hist_kernel(const void* eiv, int E, int* deg) {
    int e = blockIdx.x * 256 + threadIdx.x;
    int stride = gridDim.x * 256;
    for (; e < E; e += stride) {
        int s, d;
        load_edge(eiv, E, e, s, d);
        atomicAdd(&deg[d], 1);
    }
}

__global__ void __launch_bounds__(SCHUNK) scan_chunk_kernel(int* off, int N, int* sums) {
    __shared__ int sh[SCHUNK];
    int b = blockIdx.x;
    int i = b * SCHUNK + threadIdx.x;
    int v = (i < N) ? off[i] : 0;
    sh[threadIdx.x] = v;
    __syncthreads();
#pragma unroll
    for (int o = 1; o < SCHUNK; o <<= 1) {
        int t = (threadIdx.x >= (unsigned)o) ? sh[threadIdx.x - o] : 0;
        __syncthreads();
        sh[threadIdx.x] += t;
        __syncthreads();
    }
    if (i < N) off[i + 1] = sh[threadIdx.x];
    if (threadIdx.x == SCHUNK - 1) sums[b] = sh[threadIdx.x];
}

__global__ void __launch_bounds__(SCHUNK) scan_add_kernel(int* off, int N, const int* sums) {
    __shared__ int base_sh;
    int b = blockIdx.x;
    if (threadIdx.x == 0) {
        int base = 0;
        for (int k = 0; k < b; k++) base += sums[k];
        base_sh = base;
        if (b == 0) off[0] = 0;
    }
    __syncthreads();
    int i = b * SCHUNK + threadIdx.x;
    if (i < N) off[i + 1] += base_sh;
}

// after fill: off[d] = END of bucket d; begin(d) = (d==0) ? 0 : off[d-1]
__global__ void __launch_bounds__(256) fill_kernel(const void* eiv, int E, int* off, int* csrc) {
    int e = blockIdx.x * 256 + threadIdx.x;
    int stride = gridDim.x * 256;
    for (; e < E; e += stride) {
        int s, d;
        load_edge(eiv, E, e, s, d);
        int pos = atomicAdd(&off[d], 1);
        csrc[pos] = s;
    }
}

// ---------------- fp16 CSR gathers ----------------
// gather1: 16 lanes per row, 8 halves per lane (row = 128 halves). out fp16.
__global__ void __launch_bounds__(256) gather1_kernel(
    const __half* __restrict__ feat, const int* __restrict__ off,
    const int* __restrict__ csrc, __half* __restrict__ out, int N)
{
    int gid = blockIdx.x * 256 + threadIdx.x;
    int w = gid >> 4;
    int j = gid & 15;
    if (w >= N) return;
    int end = __ldg(&off[w]);
    int beg = (w == 0) ? 0 : __ldg(&off[w - 1]);

    float2 acc0 = make_float2(0.f, 0.f), acc1 = acc0, acc2 = acc0, acc3 = acc0;
    const __half* base = feat + j * 8;
    int k = beg;
    for (; k + 2 <= end; k += 2) {
        int s0 = __ldg(&csrc[k]);
        int s1 = __ldg(&csrc[k + 1]);
        uint4 r0 = *(const uint4*)(base + (size_t)s0 * D_IN);
        uint4 r1 = *(const uint4*)(base + (size_t)s1 * D_IN);
        float2 f;
        f = __half22float2(*(__half2*)&r0.x); acc0.x += f.x; acc0.y += f.y;
        f = __half22float2(*(__half2*)&r0.y); acc1.x += f.x; acc1.y += f.y;
        f = __half22float2(*(__half2*)&r0.z); acc2.x += f.x; acc2.y += f.y;
        f = __half22float2(*(__half2*)&r0.w); acc3.x += f.x; acc3.y += f.y;
        f = __half22float2(*(__half2*)&r1.x); acc0.x += f.x; acc0.y += f.y;
        f = __half22float2(*(__half2*)&r1.y); acc1.x += f.x; acc1.y += f.y;
        f = __half22float2(*(__half2*)&r1.z); acc2.x += f.x; acc2.y += f.y;
        f = __half22float2(*(__half2*)&r1.w); acc3.x += f.x; acc3.y += f.y;
    }
    if (k < end) {
        int s0 = __ldg(&csrc[k]);
        uint4 r0 = *(const uint4*)(base + (size_t)s0 * D_IN);
        float2 f;
        f = __half22float2(*(__half2*)&r0.x); acc0.x += f.x; acc0.y += f.y;
        f = __half22float2(*(__half2*)&r0.y); acc1.x += f.x; acc1.y += f.y;
        f = __half22float2(*(__half2*)&r0.z); acc2.x += f.x; acc2.y += f.y;
        f = __half22float2(*(__half2*)&r0.w); acc3.x += f.x; acc3.y += f.y;
    }
    uint4 o;
    *(__half2*)&o.x = __float22half2_rn(acc0);
    *(__half2*)&o.y = __float22half2_rn(acc1);
    *(__half2*)&o.z = __float22half2_rn(acc2);
    *(__half2*)&o.w = __float22half2_rn(acc3);
    *(uint4*)(out + (size_t)w * D_HID + j * 8) = o;
}

// gather2: 4 lanes per row, 8 halves per lane (row = 32 halves). out fp32 [N,32].
__global__ void __launch_bounds__(256) gather2_kernel(
    const __half* __restrict__ feat, const int* __restrict__ off,
    const int* __restrict__ csrc, float* __restrict__ out, int N)
{
    int gid = blockIdx.x * 256 + threadIdx.x;
    int w = gid >> 2;
    int j = gid & 3;
    if (w >= N) return;
    int end = __ldg(&off[w]);
    int beg = (w == 0) ? 0 : __ldg(&off[w - 1]);

    float2 acc0 = make_float2(0.f, 0.f), acc1 = acc0, acc2 = acc0, acc3 = acc0;
    const __half* base = feat + j * 8;
    for (int k = beg; k < end; k++) {
        int s0 = __ldg(&csrc[k]);
        uint4 r0 = *(const uint4*)(base + (size_t)s0 * 32);
        float2 f;
        f = __half22float2(*(__half2*)&r0.x); acc0.x += f.x; acc0.y += f.y;
        f = __half22float2(*(__half2*)&r0.y); acc1.x += f.x; acc1.y += f.y;
        f = __half22float2(*(__half2*)&r0.z); acc2.x += f.x; acc2.y += f.y;
        f = __half22float2(*(__half2*)&r0.w); acc3.x += f.x; acc3.y += f.y;
    }
    float* op = out + (size_t)w * D_OUT + j * 8;
    *(float4*)(op + 0) = make_float4(acc0.x, acc0.y, acc1.x, acc1.y);
    *(float4*)(op + 4) = make_float4(acc2.x, acc2.y, acc3.x, acc3.y);
}

// ---------------- misc ----------------
__global__ void prep_w_kernel(const float* __restrict__ Wrel2,
                              const float* __restrict__ Wroot2,
                              float* __restrict__ wcat2) {
    int i = blockIdx.x * blockDim.x + threadIdx.x;
    if (i < 128 * 64) {
        int r = i >> 6, c = i & 63;
        wcat2[i] = (c < 32) ? Wrel2[r * 32 + c] : Wroot2[r * 32 + (c - 32)];
    }
}

// ---------------- gemm1: h1 = agg1h(half)@Wrel1 + x(f32)@Wroot1 + b; fused BN1 stats ----------------
__global__ void __launch_bounds__(256) gemm1_kernel(
    const __half* __restrict__ Ah, const float* __restrict__ Ba,
    const float* __restrict__ Af, const float* __restrict__ Bb,
    const float* __restrict__ bias, float* __restrict__ C, int M,
    double* __restrict__ sumd, double* __restrict__ sqd)
{
    constexpr int BM = 128, BK = 32, BN = 128, WN = 64, NT = 8;
    __shared__ unsigned As[BM][BK + 4];
    __shared__ unsigned Bs[BK][BN + 8];
    __shared__ float shs[BN], shq[BN];

    const int tid = threadIdx.x;
    const int lane = tid & 31;
    const int wid = tid >> 5;
    const int warp_m = wid & 3;
    const int warp_n = wid >> 2;
    const int m0 = blockIdx.x * BM;
    const int tg = lane & 3;
    const int gi = lane >> 2;

    if (tid < BN) { shs[tid] = 0.f; shq[tid] = 0.f; }

    float acc[2][NT][4];
#pragma unroll
    for (int mt = 0; mt < 2; mt++)
#pragma unroll
        for (int nt = 0; nt < NT; nt++)
#pragma unroll
            for (int r = 0; r < 4; r++) acc[mt][nt][r] = 0.f;

    for (int it = 0; it < 8; it++) {
        bool halfPhase = (it < 4);
        int kloc = (it & 3) * BK;
        // ---- stage A ----
        if (halfPhase) {
#pragma unroll
            for (int t = 0; t < 2; t++) {            // 2 x uint4 (8 halves) per thread
                int v = tid + t * 256;
                int row = v >> 2;
                int c8 = (v & 3) << 3;
                unsigned u[8];
                if (m0 + row < M) {
                    uint4 rw = *(const uint4*)(Ah + (size_t)(m0 + row) * D_HID + kloc + c8);
                    float2 f;
                    f = __half22float2(*(__half2*)&rw.x); u[0] = f2tf32(f.x); u[1] = f2tf32(f.y);
                    f = __half22float2(*(__half2*)&rw.y); u[2] = f2tf32(f.x); u[3] = f2tf32(f.y);
                    f = __half22float2(*(__half2*)&rw.z); u[4] = f2tf32(f.x); u[5] = f2tf32(f.y);
                    f = __half22float2(*(__half2*)&rw.w); u[6] = f2tf32(f.x); u[7] = f2tf32(f.y);
                } else {
#pragma unroll
                    for (int q = 0; q < 8; q++) u[q] = 0u;
                }
#pragma unroll
                for (int q = 0; q < 8; q++) As[row][c8 + q] = u[q];
            }
        } else {
#pragma unroll
            for (int t = 0; t < 4; t++) {            // 4 x float4 per thread
                int v = tid + t * 256;
                int row = v >> 3;
                int c4 = (v & 7) << 2;
                float4 val = make_float4(0.f, 0.f, 0.f, 0.f);
                if (m0 + row < M)
                    val = *(const float4*)(Af + (size_t)(m0 + row) * D_IN + kloc + c4);
                As[row][c4 + 0] = f2tf32(val.x);
                As[row][c4 + 1] = f2tf32(val.y);
                As[row][c4 + 2] = f2tf32(val.z);
                As[row][c4 + 3] = f2tf32(val.w);
            }
        }
        // ---- stage B ----
        const float* B = halfPhase ? Ba : Bb;
#pragma unroll
        for (int t = 0; t < 4; t++) {
            int v = tid + t * 256;
            int kr = v >> 5;
            int c4 = (v & 31) << 2;
            float4 val = *(const float4*)(B + (size_t)(kloc + kr) * BN + c4);
            Bs[kr][c4 + 0] = f2tf32(val.x);
            Bs[kr][c4 + 1] = f2tf32(val.y);
            Bs[kr][c4 + 2] = f2tf32(val.z);
            Bs[kr][c4 + 3] = f2tf32(val.w);
        }
        __syncthreads();

#pragma unroll
        for (int ks = 0; ks < BK / 8; ks++) {
            int k8 = ks * 8;
            unsigned a[2][4];
#pragma unroll
            for (int mt = 0; mt < 2; mt++) {
                int rb = warp_m * 32 + mt * 16;
                a[mt][0] = As[rb + gi][k8 + tg];
                a[mt][1] = As[rb + 8 + gi][k8 + tg];
                a[mt][2] = As[rb + gi][k8 + 4 + tg];
                a[mt][3] = As[rb + 8 + gi][k8 + 4 + tg];
            }
            unsigned b[NT][2];
#pragma unroll
            for (int nt = 0; nt < NT; nt++) {
                int col = warp_n * WN + nt * 8 + gi;
                b[nt][0] = Bs[k8 + tg][col];
                b[nt][1] = Bs[k8 + 4 + tg][col];
            }
#pragma unroll
            for (int mt = 0; mt < 2; mt++)
#pragma unroll
                for (int nt = 0; nt < NT; nt++)
                    mma_tf32(acc[mt][nt], a[mt], b[nt]);
        }
        __syncthreads();
    }

    // ---- epilogue: bias, store, fused column stats ----
#pragma unroll
    for (int nt = 0; nt < NT; nt++) {
        int col = warp_n * WN + nt * 8 + tg * 2;
        float bx = __ldg(&bias[col]);
        float by = __ldg(&bias[col + 1]);
        float s0 = 0.f, s1 = 0.f, q0 = 0.f, q1 = 0.f;
#pragma unroll
        for (int mt = 0; mt < 2; mt++) {
            int r0 = m0 + warp_m * 32 + mt * 16 + gi;
            int r1 = r0 + 8;
            float vx = acc[mt][nt][0] + bx, vy = acc[mt][nt][1] + by;
            float wx = acc[mt][nt][2] + bx, wy = acc[mt][nt][3] + by;
            if (r0 < M) {
                *(float2*)(C + (size_t)r0 * BN + col) = make_float2(vx, vy);
                s0 += vx; q0 += vx * vx; s1 += vy; q1 += vy * vy;
            }
            if (r1 < M) {
                *(float2*)(C + (size_t)r1 * BN + col) = make_float2(wx, wy);
                s0 += wx; q0 += wx * wx; s1 += wy; q1 += wy * wy;
            }
        }
#pragma unroll
        for (int msk = 4; msk < 32; msk <<= 1) {
            s0 += __shfl_xor_sync(0xffffffffu, s0, msk);
            s1 += __shfl_xor_sync(0xffffffffu, s1, msk);
            q0 += __shfl_xor_sync(0xffffffffu, q0, msk);
            q1 += __shfl_xor_sync(0xffffffffu, q1, msk);
        }
        if (gi == 0) {
            atomicAdd(&shs[col], s0);
            atomicAdd(&shs[col + 1], s1);
            atomicAdd(&shq[col], q0);
            atomicAdd(&shq[col + 1], q1);
        }
    }
    __syncthreads();
    if (tid < BN) {
        atomicAdd(&sumd[tid], (double)shs[tid]);
        atomicAdd(&sqd[tid], (double)shq[tid]);
    }
}

// ---------------- gemm2: [t16 | r2] = relu(bn(h1)) @ wcat2 ----------------
// warp_n==0 -> cols 0..31 stored fp16 into t16; warp_n==1 -> cols 32..63 fp32 into tr.
__global__ void __launch_bounds__(256) gemm2_kernel(
    const float* __restrict__ A, const float* __restrict__ B,
    float* __restrict__ tr, __half* __restrict__ t16, int M,
    const float* __restrict__ ascale, const float* __restrict__ ashift)
{
    constexpr int BM = 128, BK = 32, BN = 64, WN = 32, NT = 4;
    __shared__ unsigned As[BM][BK + 4];
    __shared__ unsigned Bs[BK][BN + 8];

    const int tid = threadIdx.x;
    const int lane = tid & 31;
    const int wid = tid >> 5;
    const int warp_m = wid & 3;
    const int warp_n = wid >> 2;
    const int m0 = blockIdx.x * BM;
    const int tg = lane & 3;
    const int gi = lane >> 2;

    float acc[2][NT][4];
#pragma unroll
    for (int mt = 0; mt < 2; mt++)
#pragma unroll
        for (int nt = 0; nt < NT; nt++)
#pragma unroll
            for (int r = 0; r < 4; r++) acc[mt][nt][r] = 0.f;

    for (int kc = 0; kc < D_HID; kc += BK) {
#pragma unroll
        for (int t = 0; t < 4; t++) {
            int v = tid + t * 256;
            int row = v >> 3;
            int c4 = (v & 7) << 2;
            float4 val = make_float4(0.f, 0.f, 0.f, 0.f);
            if (m0 + row < M)
                val = *(const float4*)(A + (size_t)(m0 + row) * D_HID + kc + c4);
            int kg = kc + c4;
            val.x = fmaxf(fmaf(val.x, __ldg(&ascale[kg + 0]), __ldg(&ashift[kg + 0])), 0.f);
            val.y = fmaxf(fmaf(val.y, __ldg(&ascale[kg + 1]), __ldg(&ashift[kg + 1])), 0.f);
            val.z = fmaxf(fmaf(val.z, __ldg(&ascale[kg + 2]), __ldg(&ashift[kg + 2])), 0.f);
            val.w = fmaxf(fmaf(val.w, __ldg(&ascale[kg + 3]), __ldg(&ashift[kg + 3])), 0.f);
            As[row][c4 + 0] = f2tf32(val.x);
            As[row][c4 + 1] = f2tf32(val.y);
            As[row][c4 + 2] = f2tf32(val.z);
            As[row][c4 + 3] = f2tf32(val.w);
        }
#pragma unroll
        for (int t = 0; t < 2; t++) {
            int v = tid + t * 256;
            int kr = v >> 4;
            int c4 = (v & 15) << 2;
            float4 val = *(const float4*)(B + (size_t)(kc + kr) * BN + c4);
            Bs[kr][c4 + 0] = f2tf32(val.x);
            Bs[kr][c4 + 1] = f2tf32(val.y);
            Bs[kr][c4 + 2] = f2tf32(val.z);
            Bs[kr][c4 + 3] = f2tf32(val.w);
        }
        __syncthreads();

#pragma unroll
        for (int ks = 0; ks < BK / 8; ks++) {
            int k8 = ks * 8;
            unsigned a[2][4];
#pragma unroll
            for (int mt = 0; mt < 2; mt++) {
                int rb = warp_m * 32 + mt * 16;
                a[mt][0] = As[rb + gi][k8 + tg];
                a[mt][1] = As[rb + 8 + gi][k8 + tg];
                a[mt][2] = As[rb + gi][k8 + 4 + tg];
                a[mt][3] = As[rb + 8 + gi][k8 + 4 + tg];
            }
            unsigned b[NT][2];
#pragma unroll
            for (int nt = 0; nt < NT; nt++) {
                int col = warp_n * WN + nt * 8 + gi;
                b[nt][0] = Bs[k8 + tg][col];
                b[nt][1] = Bs[k8 + 4 + tg][col];
            }
#pragma unroll
            for (int mt = 0; mt < 2; mt++)
#pragma unroll
                for (int nt = 0; nt < NT; nt++)
                    mma_tf32(acc[mt][nt], a[mt], b[nt]);
        }
        __syncthreads();
    }

#pragma unroll
    for (int mt = 0; mt < 2; mt++) {
        int r0 = m0 + warp_m * 32 + mt * 16 + gi;
        int r1 = r0 + 8;
#pragma unroll
        for (int nt = 0; nt < NT; nt++) {
            int col = warp_n * WN + nt * 8 + tg * 2;
            if (warp_n == 0) {
                if (r0 < M)
                    *(__half2*)(t16 + (size_t)r0 * 32 + col) =
                        __floats2half2_rn(acc[mt][nt][0], acc[mt][nt][1]);
                if (r1 < M)
                    *(__half2*)(t16 + (size_t)r1 * 32 + col) =
                        __floats2half2_rn(acc[mt][nt][2], acc[mt][nt][3]);
            } else {
                if (r0 < M)
                    *(float2*)(tr + (size_t)r0 * 64 + col) =
                        make_float2(acc[mt][nt][0], acc[mt][nt][1]);
                if (r1 < M)
                    *(float2*)(tr + (size_t)r1 * 64 + col) =
                        make_float2(acc[mt][nt][2], acc[mt][nt][3]);
            }
        }
    }
}

// ---------------- stats / BN tail ----------------
__global__ void __launch_bounds__(256) combine_stats_kernel(
    float* __restrict__ agg2, const float* __restrict__ tr,
    const float* __restrict__ b, long long n,
    double* __restrict__ sum, double* __restrict__ sq)
{
    long long i = (long long)blockIdx.x * 256 + threadIdx.x;
    long long stride = (long long)gridDim.x * 256;
    double ls = 0.0, lq = 0.0;
    for (; i < n; i += stride) {
        long long row = i >> 5;
        int c = (int)(i & 31);
        float v = agg2[i] + __ldg(&tr[row * 64 + 32 + c]) + __ldg(&b[c]);
        agg2[i] = v;
        ls += v;
        lq += (double)v * v;
    }
    __shared__ double shA[256], shB[256];
    int tid = threadIdx.x;
    shA[tid] = ls; shB[tid] = lq;
    __syncthreads();
    for (int off = 128; off >= 32; off >>= 1) {
        if (tid < off) { shA[tid] += shA[tid + off]; shB[tid] += shB[tid + off]; }
        __syncthreads();
    }
    if (tid < 32) {
        atomicAdd(&sum[tid], shA[tid]);
        atomicAdd(&sq[tid], shB[tid]);
    }
}

__global__ void bn_finalize_kernel(
    const double* __restrict__ sum, const double* __restrict__ sq,
    const float* __restrict__ gamma, const float* __restrict__ beta,
    float* __restrict__ scale, float* __restrict__ shift, float invM)
{
    int c = threadIdx.x;
    double mu = sum[c] * (double)invM;
    double var = sq[c] * (double)invM - mu * mu;
    float s = gamma[c] * rsqrtf((float)var + 1e-5f);
    scale[c] = s;
    shift[c] = beta[c] - (float)mu * s;
}

__global__ void __launch_bounds__(256) bn_relu_kernel(
    const float* __restrict__ in, float* __restrict__ out, long long n, int mask,
    const float* __restrict__ scale, const float* __restrict__ shift)
{
    long long i = (long long)blockIdx.x * blockDim.x + threadIdx.x;
    long long stride = (long long)gridDim.x * blockDim.x;
    for (; i < n; i += stride) {
        int c = (int)(i & mask);
        float v = fmaf(in[i], __ldg(&scale[c]), __ldg(&shift[c]));
        out[i] = fmaxf(v, 0.f);
    }
}

static inline int ceil_div_i(int a, int b) { return (a + b - 1) / b; }

// ---------------- launch ----------------
extern "C" void kernel_launch(void* const* d_in, const int* in_sizes, int n_in,
                              void* d_out, int out_size)
{
    const float* x      = (const float*)d_in[0];
    const void*  ei     = d_in[1];
    const float* Wrel1  = (const float*)d_in[2];
    const float* brel1  = (const float*)d_in[3];
    const float* Wroot1 = (const float*)d_in[4];
    const float* gamma1 = (const float*)d_in[5];
    const float* beta1  = (const float*)d_in[6];
    const float* Wrel2  = (const float*)d_in[7];
    const float* brel2  = (const float*)d_in[8];
    const float* Wroot2 = (const float*)d_in[9];
    const float* gamma2 = (const float*)d_in[10];
    const float* beta2  = (const float*)d_in[11];

    const int N = in_sizes[0] / D_IN;
    const int E = in_sizes[1] / 2;

    float *h1, *tr, *agg2, *ss, *wcat2;
    __half *x16, *agg1h, *t16;
    double* stats;
    int *off, *sums, *csrc;
    cudaGetSymbolAddress((void**)&x16, g_x16);
    cudaGetSymbolAddress((void**)&agg1h, g_agg1h);
    cudaGetSymbolAddress((void**)&h1, g_h1);
    cudaGetSymbolAddress((void**)&tr, g_tr);
    cudaGetSymbolAddress((void**)&t16, g_t16);
    cudaGetSymbolAddress((void**)&agg2, g_agg2);
    cudaGetSymbolAddress((void**)&stats, g_stats);
    cudaGetSymbolAddress((void**)&ss, g_ss);
    cudaGetSymbolAddress((void**)&wcat2, g_wcat2);
    cudaGetSymbolAddress((void**)&off, g_off);
    cudaGetSymbolAddress((void**)&sums, g_sums);
    cudaGetSymbolAddress((void**)&csrc, g_csrc);

    const int nchunks = ceil_div_i(N, SCHUNK);
    const int eblocks = ceil_div_i(E, 256);

    // #0: zero off + stats, detect dtype, convert x -> fp16
    init_kernel<<<2048, 256>>>((const int*)ei, E, off, N, stats, x, x16,
                               (long long)N * D_IN / 2);
    hist_kernel<<<eblocks, 256>>>(ei, E, off);                        // #1
    scan_chunk_kernel<<<nchunks, SCHUNK>>>(off, N, sums);             // #2
    scan_add_kernel<<<nchunks, SCHUNK>>>(off, N, sums);               // #3
    fill_kernel<<<eblocks, 256>>>(ei, E, off, csrc);                  // #4

    // #5 (profiled): fp16 gather in 128-d
    gather1_kernel<<<ceil_div_i(N * 16, 256), 256>>>(x16, off, csrc, agg1h, N);

    // #6: h1 = agg1h@Wrel1 + x@Wroot1 + b, fused BN1 stats
    gemm1_kernel<<<ceil_div_i(N, 128), 256>>>(
        agg1h, Wrel1, x, Wroot1, brel1, h1, N, stats, stats + 128);
    bn_finalize_kernel<<<1, 128>>>(stats, stats + 128, gamma1, beta1, ss, ss + 128,
                                   1.0f / (float)N);
    prep_w_kernel<<<32, 256>>>(Wrel2, Wroot2, wcat2);

    // layer 2: project first (t fp16, r2 fp32), then gather in 32-d
    gemm2_kernel<<<ceil_div_i(N, 128), 256>>>(h1, wcat2, tr, t16, N, ss, ss + 128);
    gather2_kernel<<<ceil_div_i(N * 4, 256), 256>>>(t16, off, csrc, agg2, N);

    combine_stats_kernel<<<512, 256>>>(agg2, tr, brel2, (long long)N * D_OUT,
                                       stats + 256, stats + 288);
    bn_finalize_kernel<<<1, 32>>>(stats + 256, stats + 288, gamma2, beta2,
                                  ss + 256, ss + 288, 1.0f / (float)N);
    bn_relu_kernel<<<1024, 256>>>(agg2, (float*)d_out, (long long)N * D_OUT, D_OUT - 1,
                                  ss + 256, ss + 288);
}

// round 8
// speedup vs baseline: 4.4895x; 1.2062x over previous
#include <cuda_runtime.h>
#include <cuda_fp16.h>
#include <cstddef>

#define D_IN  128
#define D_HID 128
#define D_OUT 32
#define NMAX  100000
#define EMAX  1601000
#define SCHUNK 1024

// ---------------- static device scratch (no runtime allocation) ----------------
__device__ __half g_x16 [(size_t)NMAX * D_IN];    // fp16 copy of x
__device__ __half g_agg1h[(size_t)NMAX * D_HID];  // gathered x (fp16)
__device__ float  g_h1  [(size_t)NMAX * D_HID];   // pre-BN h1
__device__ float  g_tr  [(size_t)NMAX * 64];      // cols 32..63 = r2 (fp32)
__device__ __half g_t16 [(size_t)NMAX * 32];      // t = relu(bn(h1))@W_rel2 (fp16)
__device__ float  g_agg2[(size_t)NMAX * D_OUT];
__device__ double g_stats[320];
__device__ float  g_ss[320];
__device__ __half g_w1hT [128 * 256];             // [n][k] : k<128 Wrel1, k>=128 Wroot1
__device__ __half g_w2hT [64 * 128];              // [n][k] : n<32 Wrel2, n>=32 Wroot2
__device__ int    g_off[NMAX + 1];
__device__ int    g_sums[128];
__device__ int    g_csrc[EMAX];
__device__ int    g_is64;

// ---------------- fp16 MMA helper ----------------
__device__ __forceinline__ void mma_f16(float c[4], const unsigned a[4], const unsigned b[2]) {
    asm volatile(
        "mma.sync.aligned.m16n8k16.row.col.f32.f16.f16.f32 "
        "{%0,%1,%2,%3}, {%4,%5,%6,%7}, {%8,%9}, {%0,%1,%2,%3};"
        : "+f"(c[0]), "+f"(c[1]), "+f"(c[2]), "+f"(c[3])
        : "r"(a[0]), "r"(a[1]), "r"(a[2]), "r"(a[3]), "r"(b[0]), "r"(b[1]));
}

// ---------------- launch #0: zeros + dtype detect + x->fp16 + weight prep ----------------
__global__ void __launch_bounds__(256) init_kernel(
    const int* ei, int E, int* off, int N, double* stats,
    const float* __restrict__ x, __half* __restrict__ x16, long long nh2,
    const float* __restrict__ Wrel1, const float* __restrict__ Wroot1,
    const float* __restrict__ Wrel2, const float* __restrict__ Wroot2,
    __half* __restrict__ w1hT, __half* __restrict__ w2hT)
{
    long long i = (long long)blockIdx.x * 256 + threadIdx.x;
    long long stride = (long long)gridDim.x * 256;
    for (long long t = i; t <= N; t += stride) off[t] = 0;
    for (long long t = i; t < 320; t += stride) stats[t] = 0.0;
    const float2* xf2 = (const float2*)x;
    __half2* xh2 = (__half2*)x16;
    for (long long t = i; t < nh2; t += stride)
        xh2[t] = __float22half2_rn(xf2[t]);
    // w1hT[n][k] = (k<128 ? Wrel1[k][n] : Wroot1[k-128][n]), n<128, k<256
    for (long long t = i; t < 128 * 256; t += stride) {
        int n = (int)(t >> 8), k = (int)(t & 255);
        float v = (k < 128) ? Wrel1[k * 128 + n] : Wroot1[(k - 128) * 128 + n];
        w1hT[t] = __float2half_rn(v);
    }
    // w2hT[n][k] = (n<32 ? Wrel2[k][n] : Wroot2[k][n-32]), n<64, k<128
    for (long long t = i; t < 64 * 128; t += stride) {
        int n = (int)(t >> 7), k = (int)(t & 127);
        float v = (n < 32) ? Wrel2[k * 32 + n] : Wroot2[k * 32 + (n - 32)];
        w2hT[t] = __float2half_rn(v);
    }
    if (blockIdx.x == 0 && threadIdx.x == 0) {
        int n = 2 * E;
        int allzero = 1;
        for (int k = 1; k < 256 && k < n; k += 2) {
            if (ei[k] != 0) { allzero = 0; break; }
        }
        g_is64 = allzero;
    }
}

__device__ __forceinline__ void load_edge(const void* eiv, int E, int e, int& s, int& d) {
    if (g_is64) {
        const long long* p = (const long long*)eiv;
        s = (int)p[e];
        d = (int)p[(size_t)E + e];
    } else {
        const int* p = (const int*)eiv;
        s = p[e];
        d = p[E + e];
    }
}

// ---------------- CSR build ----------------
__global__ void __launch_bounds__(256) hist_kernel(const void* eiv, int E, int* deg) {
    int e = blockIdx.x * 256 + threadIdx.x;
    int stride = gridDim.x * 256;
    for (; e < E; e += stride) {
        int s, d;
        load_edge(eiv, E, e, s, d);
        atomicAdd(&deg[d], 1);
    }
}

__global__ void __launch_bounds__(SCHUNK) scan_chunk_kernel(int* off, int N, int* sums) {
    __shared__ int sh[SCHUNK];
    int b = blockIdx.x;
    int i = b * SCHUNK + threadIdx.x;
    int v = (i < N) ? off[i] : 0;
    sh[threadIdx.x] = v;
    __syncthreads();
#pragma unroll
    for (int o = 1; o < SCHUNK; o <<= 1) {
        int t = (threadIdx.x >= (unsigned)o) ? sh[threadIdx.x - o] : 0;
        __syncthreads();
        sh[threadIdx.x] += t;
        __syncthreads();
    }
    if (i < N) off[i + 1] = sh[threadIdx.x];
    if (threadIdx.x == SCHUNK - 1) sums[b] = sh[threadIdx.x];
}

__global__ void __launch_bounds__(SCHUNK) scan_add_kernel(int* off, int N, const int* sums) {
    __shared__ int base_sh;
    int b = blockIdx.x;
    if (threadIdx.x == 0) {
        int base = 0;
        for (int k = 0; k < b; k++) base += sums[k];
        base_sh = base;
        if (b == 0) off[0] = 0;
    }
    __syncthreads();
    int i = b * SCHUNK + threadIdx.x;
    if (i < N) off[i + 1] += base_sh;
}

// after fill: off[d] = END of bucket d; begin(d) = (d==0) ? 0 : off[d-1]
__global__ void __launch_bounds__(256) fill_kernel(const void* eiv, int E, int* off, int* csrc) {
    int e = blockIdx.x * 256 + threadIdx.x;
    int stride = gridDim.x * 256;
    for (; e < E; e += stride) {
        int s, d;
        load_edge(eiv, E, e, s, d);
        int pos = atomicAdd(&off[d], 1);
        csrc[pos] = s;
    }
}

// ---------------- gather1: 16 lanes/row, 8 halves/lane ----------------
__global__ void __launch_bounds__(256) gather1_kernel(
    const __half* __restrict__ feat, const int* __restrict__ off,
    const int* __restrict__ csrc, __half* __restrict__ out, int N)
{
    int gid = blockIdx.x * 256 + threadIdx.x;
    int w = gid >> 4;
    int j = gid & 15;
    if (w >= N) return;
    int end = __ldg(&off[w]);
    int beg = (w == 0) ? 0 : __ldg(&off[w - 1]);

    float2 acc0 = make_float2(0.f, 0.f), acc1 = acc0, acc2 = acc0, acc3 = acc0;
    const __half* base = feat + j * 8;
    int k = beg;
    for (; k + 2 <= end; k += 2) {
        int s0 = __ldg(&csrc[k]);
        int s1 = __ldg(&csrc[k + 1]);
        uint4 r0 = *(const uint4*)(base + (size_t)s0 * D_IN);
        uint4 r1 = *(const uint4*)(base + (size_t)s1 * D_IN);
        float2 f;
        f = __half22float2(*(__half2*)&r0.x); acc0.x += f.x; acc0.y += f.y;
        f = __half22float2(*(__half2*)&r0.y); acc1.x += f.x; acc1.y += f.y;
        f = __half22float2(*(__half2*)&r0.z); acc2.x += f.x; acc2.y += f.y;
        f = __half22float2(*(__half2*)&r0.w); acc3.x += f.x; acc3.y += f.y;
        f = __half22float2(*(__half2*)&r1.x); acc0.x += f.x; acc0.y += f.y;
        f = __half22float2(*(__half2*)&r1.y); acc1.x += f.x; acc1.y += f.y;
        f = __half22float2(*(__half2*)&r1.z); acc2.x += f.x; acc2.y += f.y;
        f = __half22float2(*(__half2*)&r1.w); acc3.x += f.x; acc3.y += f.y;
    }
    if (k < end) {
        int s0 = __ldg(&csrc[k]);
        uint4 r0 = *(const uint4*)(base + (size_t)s0 * D_IN);
        float2 f;
        f = __half22float2(*(__half2*)&r0.x); acc0.x += f.x; acc0.y += f.y;
        f = __half22float2(*(__half2*)&r0.y); acc1.x += f.x; acc1.y += f.y;
        f = __half22float2(*(__half2*)&r0.z); acc2.x += f.x; acc2.y += f.y;
        f = __half22float2(*(__half2*)&r0.w); acc3.x += f.x; acc3.y += f.y;
    }
    uint4 o;
    *(__half2*)&o.x = __float22half2_rn(acc0);
    *(__half2*)&o.y = __float22half2_rn(acc1);
    *(__half2*)&o.z = __float22half2_rn(acc2);
    *(__half2*)&o.w = __float22half2_rn(acc3);
    *(uint4*)(out + (size_t)w * D_HID + j * 8) = o;
}

// ---------------- gemm1: h1 = [agg1h | x16] @ w1hT' + b; fused BN1 stats ----------------
// fp16 m16n8k16 MMA, fp32 accum. Block 128x128, 8 warps (4m x 2n).
__global__ void __launch_bounds__(256) gemm1_kernel(
    const __half* __restrict__ Ah, const __half* __restrict__ Axh,
    const __half* __restrict__ w1hT,
    const float* __restrict__ bias, float* __restrict__ C, int M,
    double* __restrict__ sumd, double* __restrict__ sqd)
{
    constexpr int BM = 128, BK = 32, BN = 128, WN = 64, NT = 8;
    constexpr int KPAD = 8;  // row stride 40 halves = 80B (16B-aligned)
    __shared__ __half As[BM][BK + KPAD];
    __shared__ __half BsT[BN][BK + KPAD];   // [n][k]
    __shared__ float shs[BN], shq[BN];

    const int tid = threadIdx.x;
    const int lane = tid & 31;
    const int wid = tid >> 5;
    const int warp_m = wid & 3;
    const int warp_n = wid >> 2;
    const int m0 = blockIdx.x * BM;
    const int tg = lane & 3;
    const int gi = lane >> 2;

    if (tid < BN) { shs[tid] = 0.f; shq[tid] = 0.f; }

    float acc[2][NT][4];
#pragma unroll
    for (int mt = 0; mt < 2; mt++)
#pragma unroll
        for (int nt = 0; nt < NT; nt++)
#pragma unroll
            for (int r = 0; r < 4; r++) acc[mt][nt][r] = 0.f;

    for (int it = 0; it < 8; it++) {
        const __half* Asrc = (it < 4) ? Ah : Axh;
        int kloc = (it & 3) * BK;
        int kglob = it * BK;
        // stage A: 128x32 halves = 512 uint4, 2 per thread
#pragma unroll
        for (int t = 0; t < 2; t++) {
            int v = tid + t * 256;
            int row = v >> 2;
            int c8 = (v & 3) << 3;
            uint4 rw = make_uint4(0, 0, 0, 0);
            if (m0 + row < M)
                rw = *(const uint4*)(Asrc + (size_t)(m0 + row) * 128 + kloc + c8);
            *(uint4*)&As[row][c8] = rw;
        }
        // stage B transposed: BsT[n][k] from w1hT[n*256 + kglob + k]
#pragma unroll
        for (int t = 0; t < 2; t++) {
            int v = tid + t * 256;
            int n = v >> 2;
            int c8 = (v & 3) << 3;
            uint4 rw = *(const uint4*)(w1hT + (size_t)n * 256 + kglob + c8);
            *(uint4*)&BsT[n][c8] = rw;
        }
        __syncthreads();

#pragma unroll
        for (int ks = 0; ks < 2; ks++) {
            int k16 = ks * 16;
            unsigned a[2][4];
#pragma unroll
            for (int mt = 0; mt < 2; mt++) {
                int rb = warp_m * 32 + mt * 16;
                a[mt][0] = *(const unsigned*)&As[rb + gi][k16 + 2 * tg];
                a[mt][1] = *(const unsigned*)&As[rb + 8 + gi][k16 + 2 * tg];
                a[mt][2] = *(const unsigned*)&As[rb + gi][k16 + 8 + 2 * tg];
                a[mt][3] = *(const unsigned*)&As[rb + 8 + gi][k16 + 8 + 2 * tg];
            }
            unsigned b[NT][2];
#pragma unroll
            for (int nt = 0; nt < NT; nt++) {
                int col = warp_n * WN + nt * 8 + gi;
                b[nt][0] = *(const unsigned*)&BsT[col][k16 + 2 * tg];
                b[nt][1] = *(const unsigned*)&BsT[col][k16 + 8 + 2 * tg];
            }
#pragma unroll
            for (int mt = 0; mt < 2; mt++)
#pragma unroll
                for (int nt = 0; nt < NT; nt++)
                    mma_f16(acc[mt][nt], a[mt], b[nt]);
        }
        __syncthreads();
    }

    // epilogue: bias, store, fused column stats
#pragma unroll
    for (int nt = 0; nt < NT; nt++) {
        int col = warp_n * WN + nt * 8 + tg * 2;
        float bx = __ldg(&bias[col]);
        float by = __ldg(&bias[col + 1]);
        float s0 = 0.f, s1 = 0.f, q0 = 0.f, q1 = 0.f;
#pragma unroll
        for (int mt = 0; mt < 2; mt++) {
            int r0 = m0 + warp_m * 32 + mt * 16 + gi;
            int r1 = r0 + 8;
            float vx = acc[mt][nt][0] + bx, vy = acc[mt][nt][1] + by;
            float wx = acc[mt][nt][2] + bx, wy = acc[mt][nt][3] + by;
            if (r0 < M) {
                *(float2*)(C + (size_t)r0 * BN + col) = make_float2(vx, vy);
                s0 += vx; q0 += vx * vx; s1 += vy; q1 += vy * vy;
            }
            if (r1 < M) {
                *(float2*)(C + (size_t)r1 * BN + col) = make_float2(wx, wy);
                s0 += wx; q0 += wx * wx; s1 += wy; q1 += wy * wy;
            }
        }
#pragma unroll
        for (int msk = 4; msk < 32; msk <<= 1) {
            s0 += __shfl_xor_sync(0xffffffffu, s0, msk);
            s1 += __shfl_xor_sync(0xffffffffu, s1, msk);
            q0 += __shfl_xor_sync(0xffffffffu, q0, msk);
            q1 += __shfl_xor_sync(0xffffffffu, q1, msk);
        }
        if (gi == 0) {
            atomicAdd(&shs[col], s0);
            atomicAdd(&shs[col + 1], s1);
            atomicAdd(&shq[col], q0);
            atomicAdd(&shq[col + 1], q1);
        }
    }
    __syncthreads();
    if (tid < BN) {
        atomicAdd(&sumd[tid], (double)shs[tid]);
        atomicAdd(&sqd[tid], (double)shq[tid]);
    }
}

// ---------------- gemm2: [t16 | r2] = relu(bn(h1)) @ w2hT' ----------------
__global__ void __launch_bounds__(256) gemm2_kernel(
    const float* __restrict__ A, const __half* __restrict__ w2hT,
    float* __restrict__ tr, __half* __restrict__ t16, int M,
    const float* __restrict__ ascale, const float* __restrict__ ashift)
{
    constexpr int BM = 128, BK = 32, BN = 64, WN = 32, NT = 4;
    constexpr int KPAD = 8;
    __shared__ __half As[BM][BK + KPAD];
    __shared__ __half BsT[BN][BK + KPAD];

    const int tid = threadIdx.x;
    const int lane = tid & 31;
    const int wid = tid >> 5;
    const int warp_m = wid & 3;
    const int warp_n = wid >> 2;
    const int m0 = blockIdx.x * BM;
    const int tg = lane & 3;
    const int gi = lane >> 2;

    float acc[2][NT][4];
#pragma unroll
    for (int mt = 0; mt < 2; mt++)
#pragma unroll
        for (int nt = 0; nt < NT; nt++)
#pragma unroll
            for (int r = 0; r < 4; r++) acc[mt][nt][r] = 0.f;

    for (int kc = 0; kc < D_HID; kc += BK) {
        // stage A with BN+relu, fp32 -> fp16
#pragma unroll
        for (int t = 0; t < 4; t++) {
            int v = tid + t * 256;
            int row = v >> 3;
            int c4 = (v & 7) << 2;
            float4 val = make_float4(0.f, 0.f, 0.f, 0.f);
            if (m0 + row < M)
                val = *(const float4*)(A + (size_t)(m0 + row) * D_HID + kc + c4);
            int kg = kc + c4;
            val.x = fmaxf(fmaf(val.x, __ldg(&ascale[kg + 0]), __ldg(&ashift[kg + 0])), 0.f);
            val.y = fmaxf(fmaf(val.y, __ldg(&ascale[kg + 1]), __ldg(&ashift[kg + 1])), 0.f);
            val.z = fmaxf(fmaf(val.z, __ldg(&ascale[kg + 2]), __ldg(&ashift[kg + 2])), 0.f);
            val.w = fmaxf(fmaf(val.w, __ldg(&ascale[kg + 3]), __ldg(&ashift[kg + 3])), 0.f);
            uint2 pk;
            *(__half2*)&pk.x = __floats2half2_rn(val.x, val.y);
            *(__half2*)&pk.y = __floats2half2_rn(val.z, val.w);
            *(uint2*)&As[row][c4] = pk;
        }
        // stage B transposed: 64x32 halves = 256 uint4, 1 per thread
        {
            int n = tid >> 2;
            int c8 = (tid & 3) << 3;
            uint4 rw = *(const uint4*)(w2hT + (size_t)n * 128 + kc + c8);
            *(uint4*)&BsT[n][c8] = rw;
        }
        __syncthreads();

#pragma unroll
        for (int ks = 0; ks < 2; ks++) {
            int k16 = ks * 16;
            unsigned a[2][4];
#pragma unroll
            for (int mt = 0; mt < 2; mt++) {
                int rb = warp_m * 32 + mt * 16;
                a[mt][0] = *(const unsigned*)&As[rb + gi][k16 + 2 * tg];
                a[mt][1] = *(const unsigned*)&As[rb + 8 + gi][k16 + 2 * tg];
                a[mt][2] = *(const unsigned*)&As[rb + gi][k16 + 8 + 2 * tg];
                a[mt][3] = *(const unsigned*)&As[rb + 8 + gi][k16 + 8 + 2 * tg];
            }
            unsigned b[NT][2];
#pragma unroll
            for (int nt = 0; nt < NT; nt++) {
                int col = warp_n * WN + nt * 8 + gi;
                b[nt][0] = *(const unsigned*)&BsT[col][k16 + 2 * tg];
                b[nt][1] = *(const unsigned*)&BsT[col][k16 + 8 + 2 * tg];
            }
#pragma unroll
            for (int mt = 0; mt < 2; mt++)
#pragma unroll
                for (int nt = 0; nt < NT; nt++)
                    mma_f16(acc[mt][nt], a[mt], b[nt]);
        }
        __syncthreads();
    }

#pragma unroll
    for (int mt = 0; mt < 2; mt++) {
        int r0 = m0 + warp_m * 32 + mt * 16 + gi;
        int r1 = r0 + 8;
#pragma unroll
        for (int nt = 0; nt < NT; nt++) {
            int col = warp_n * WN + nt * 8 + tg * 2;
            if (warp_n == 0) {
                if (r0 < M)
                    *(__half2*)(t16 + (size_t)r0 * 32 + col) =
                        __floats2half2_rn(acc[mt][nt][0], acc[mt][nt][1]);
                if (r1 < M)
                    *(__half2*)(t16 + (size_t)r1 * 32 + col) =
                        __floats2half2_rn(acc[mt][nt][2], acc[mt][nt][3]);
            } else {
                if (r0 < M)
                    *(float2*)(tr + (size_t)r0 * 64 + col) =
                        make_float2(acc[mt][nt][0], acc[mt][nt][1]);
                if (r1 < M)
                    *(float2*)(tr + (size_t)r1 * 64 + col) =
                        make_float2(acc[mt][nt][2], acc[mt][nt][3]);
            }
        }
    }
}

// ---------------- gather2 fused: agg2 = gather(t16) + r2 + bias; BN2 stats ----------------
__global__ void __launch_bounds__(256) gather2_fused_kernel(
    const __half* __restrict__ feat, const int* __restrict__ off,
    const int* __restrict__ csrc, const float* __restrict__ tr,
    const float* __restrict__ bias, float* __restrict__ out, int N,
    double* __restrict__ sumd, double* __restrict__ sqd)
{
    __shared__ float shs[32], shq[32];
    int tid = threadIdx.x;
    if (tid < 32) { shs[tid] = 0.f; shq[tid] = 0.f; }
    __syncthreads();

    int gid = blockIdx.x * 256 + tid;
    int w = gid >> 2;
    int j = gid & 3;
    bool valid = (w < N);

    float v[8];
#pragma unroll
    for (int q = 0; q < 8; q++) v[q] = 0.f;

    if (valid) {
        int end = __ldg(&off[w]);
        int beg = (w == 0) ? 0 : __ldg(&off[w - 1]);
        const __half* base = feat + j * 8;
        for (int k = beg; k < end; k++) {
            int s0 = __ldg(&csrc[k]);
            uint4 r0 = *(const uint4*)(base + (size_t)s0 * 32);
            float2 f;
            f = __half22float2(*(__half2*)&r0.x); v[0] += f.x; v[1] += f.y;
            f = __half22float2(*(__half2*)&r0.y); v[2] += f.x; v[3] += f.y;
            f = __half22float2(*(__half2*)&r0.z); v[4] += f.x; v[5] += f.y;
            f = __half22float2(*(__half2*)&r0.w); v[6] += f.x; v[7] += f.y;
        }
        // + r2 + bias
        const float* rp = tr + (size_t)w * 64 + 32 + j * 8;
        float4 ra = *(const float4*)(rp + 0);
        float4 rb = *(const float4*)(rp + 4);
        const float* bp = bias + j * 8;
        v[0] += ra.x + __ldg(bp + 0); v[1] += ra.y + __ldg(bp + 1);
        v[2] += ra.z + __ldg(bp + 2); v[3] += ra.w + __ldg(bp + 3);
        v[4] += rb.x + __ldg(bp + 4); v[5] += rb.y + __ldg(bp + 5);
        v[6] += rb.z + __ldg(bp + 6); v[7] += rb.w + __ldg(bp + 7);
        float* op = out + (size_t)w * D_OUT + j * 8;
        *(float4*)(op + 0) = make_float4(v[0], v[1], v[2], v[3]);
        *(float4*)(op + 4) = make_float4(v[4], v[5], v[6], v[7]);
    }

    // stats: reduce across lanes with same j (butterfly over 4,8,16), then shared atomics
    float s[8], q[8];
#pragma unroll
    for (int t = 0; t < 8; t++) {
        s[t] = valid ? v[t] : 0.f;
        q[t] = valid ? v[t] * v[t] : 0.f;
    }
#pragma unroll
    for (int msk = 4; msk < 32; msk <<= 1)
#pragma unroll
        for (int t = 0; t < 8; t++) {
            s[t] += __shfl_xor_sync(0xffffffffu, s[t], msk);
            q[t] += __shfl_xor_sync(0xffffffffu, q[t], msk);
        }
    if ((tid & 31) < 4) {
#pragma unroll
        for (int t = 0; t < 8; t++) {
            atomicAdd(&shs[j * 8 + t], s[t]);
            atomicAdd(&shq[j * 8 + t], q[t]);
        }
    }
    __syncthreads();
    if (tid < 32) {
        atomicAdd(&sumd[tid], (double)shs[tid]);
        atomicAdd(&sqd[tid], (double)shq[tid]);
    }
}

// ---------------- BN finalize + final normalize/relu ----------------
__global__ void bn_finalize_kernel(
    const double* __restrict__ sum, const double* __restrict__ sq,
    const float* __restrict__ gamma, const float* __restrict__ beta,
    float* __restrict__ scale, float* __restrict__ shift, float invM)
{
    int c = threadIdx.x;
    double mu = sum[c] * (double)invM;
    double var = sq[c] * (double)invM - mu * mu;
    float s = gamma[c] * rsqrtf((float)var + 1e-5f);
    scale[c] = s;
    shift[c] = beta[c] - (float)mu * s;
}

__global__ void __launch_bounds__(256) bn_relu_kernel(
    const float* __restrict__ in, float* __restrict__ out, long long n, int mask,
    const float* __restrict__ scale, const float* __restrict__ shift)
{
    long long i = (long long)blockIdx.x * blockDim.x + threadIdx.x;
    long long stride = (long long)gridDim.x * blockDim.x;
    for (; i < n; i += stride) {
        int c = (int)(i & mask);
        float v = fmaf(in[i], __ldg(&scale[c]), __ldg(&shift[c]));
        out[i] = fmaxf(v, 0.f);
    }
}

static inline int ceil_div_i(int a, int b) { return (a + b - 1) / b; }

// ---------------- launch ----------------
extern "C" void kernel_launch(void* const* d_in, const int* in_sizes, int n_in,
                              void* d_out, int out_size)
{
    const float* x      = (const float*)d_in[0];
    const void*  ei     = d_in[1];
    const float* Wrel1  = (const float*)d_in[2];
    const float* brel1  = (const float*)d_in[3];
    const float* Wroot1 = (const float*)d_in[4];
    const float* gamma1 = (const float*)d_in[5];
    const float* beta1  = (const float*)d_in[6];
    const float* Wrel2  = (const float*)d_in[7];
    const float* brel2  = (const float*)d_in[8];
    const float* Wroot2 = (const float*)d_in[9];
    const float* gamma2 = (const float*)d_in[10];
    const float* beta2  = (const float*)d_in[11];

    const int N = in_sizes[0] / D_IN;
    const int E = in_sizes[1] / 2;

    float *h1, *tr, *agg2, *ss;
    __half *x16, *agg1h, *t16, *w1hT, *w2hT;
    double* stats;
    int *off, *sums, *csrc;
    cudaGetSymbolAddress((void**)&x16, g_x16);
    cudaGetSymbolAddress((void**)&agg1h, g_agg1h);
    cudaGetSymbolAddress((void**)&h1, g_h1);
    cudaGetSymbolAddress((void**)&tr, g_tr);
    cudaGetSymbolAddress((void**)&t16, g_t16);
    cudaGetSymbolAddress((void**)&agg2, g_agg2);
    cudaGetSymbolAddress((void**)&stats, g_stats);
    cudaGetSymbolAddress((void**)&ss, g_ss);
    cudaGetSymbolAddress((void**)&w1hT, g_w1hT);
    cudaGetSymbolAddress((void**)&w2hT, g_w2hT);
    cudaGetSymbolAddress((void**)&off, g_off);
    cudaGetSymbolAddress((void**)&sums, g_sums);
    cudaGetSymbolAddress((void**)&csrc, g_csrc);

    const int nchunks = ceil_div_i(N, SCHUNK);
    const int eblocks = ceil_div_i(E, 256);

    // #0: zeros, dtype detect, x->fp16, weight fp16 transposes
    init_kernel<<<2048, 256>>>((const int*)ei, E, off, N, stats, x, x16,
                               (long long)N * D_IN / 2,
                               Wrel1, Wroot1, Wrel2, Wroot2, w1hT, w2hT);
    hist_kernel<<<eblocks, 256>>>(ei, E, off);                        // #1
    scan_chunk_kernel<<<nchunks, SCHUNK>>>(off, N, sums);             // #2
    scan_add_kernel<<<nchunks, SCHUNK>>>(off, N, sums);               // #3
    fill_kernel<<<eblocks, 256>>>(ei, E, off, csrc);                  // #4

    // #5 (profiled): fp16 gather in 128-d
    gather1_kernel<<<ceil_div_i(N * 16, 256), 256>>>(x16, off, csrc, agg1h, N);

    // #6: h1 = agg1h@Wrel1 + x16@Wroot1 + b  (fp16 MMA, fused BN1 stats)
    gemm1_kernel<<<ceil_div_i(N, 128), 256>>>(
        agg1h, x16, w1hT, brel1, h1, N, stats, stats + 128);
    bn_finalize_kernel<<<1, 128>>>(stats, stats + 128, gamma1, beta1, ss, ss + 128,
                                   1.0f / (float)N);

    // layer 2: project first (t fp16, r2 fp32), then fused gather+combine+stats
    gemm2_kernel<<<ceil_div_i(N, 128), 256>>>(h1, w2hT, tr, t16, N, ss, ss + 128);
    gather2_fused_kernel<<<ceil_div_i(N * 4, 256), 256>>>(
        t16, off, csrc, tr, brel2, agg2, N, stats + 256, stats + 288);

    bn_finalize_kernel<<<1, 32>>>(stats + 256, stats + 288, gamma2, beta2,
                                  ss + 256, ss + 288, 1.0f / (float)N);
    bn_relu_kernel<<<1024, 256>>>(agg2, (float*)d_out, (long long)N * D_OUT, D_OUT - 1,
                                  ss + 256, ss + 288);
}

// round 9
// speedup vs baseline: 4.5292x; 1.0088x over previous
#include <cuda_runtime.h>
#include <cuda_fp16.h>
#include <cstddef>

#define D_IN  128
#define D_HID 128
#define D_OUT 32
#define NMAX  100000
#define EMAX  1601000
#define SCHUNK 1024
#define NCHUNKMAX 128

// ---------------- static device scratch (no runtime allocation) ----------------
__device__ __half g_x16 [(size_t)NMAX * D_IN];
__device__ __half g_agg1h[(size_t)NMAX * D_HID];
__device__ __half g_h1h [(size_t)NMAX * D_HID];   // pre-BN h1 (fp16)
__device__ float  g_tr  [(size_t)NMAX * 64];      // cols 32..63 = r2 (fp32)
__device__ __half g_t16 [(size_t)NMAX * 32];
__device__ float  g_agg2[(size_t)NMAX * D_OUT];
__device__ double g_stats[320];
__device__ float  g_ss[320];
__device__ __half g_w1hT [128 * 256];
__device__ __half g_w2hT [64 * 128];
__device__ int    g_off[NMAX + 1];
__device__ unsigned long long g_scan_state[NCHUNKMAX];
__device__ int    g_csrc[EMAX];
__device__ int    g_is64;

// ---------------- fp16 MMA helper ----------------
__device__ __forceinline__ void mma_f16(float c[4], const unsigned a[4], const unsigned b[2]) {
    asm volatile(
        "mma.sync.aligned.m16n8k16.row.col.f32.f16.f16.f32 "
        "{%0,%1,%2,%3}, {%4,%5,%6,%7}, {%8,%9}, {%0,%1,%2,%3};"
        : "+f"(c[0]), "+f"(c[1]), "+f"(c[2]), "+f"(c[3])
        : "r"(a[0]), "r"(a[1]), "r"(a[2]), "r"(a[3]), "r"(b[0]), "r"(b[1]));
}

// ---------------- launch #0: zeros + dtype detect + x->fp16 + weight prep ----------------
__global__ void __launch_bounds__(256) init_kernel(
    const int* ei, int E, int* off, int N, double* stats,
    const float* __restrict__ x, __half* __restrict__ x16, long long nh2,
    const float* __restrict__ Wrel1, const float* __restrict__ Wroot1,
    const float* __restrict__ Wrel2, const float* __restrict__ Wroot2,
    __half* __restrict__ w1hT, __half* __restrict__ w2hT)
{
    long long i = (long long)blockIdx.x * 256 + threadIdx.x;
    long long stride = (long long)gridDim.x * 256;
    for (long long t = i; t <= N; t += stride) off[t] = 0;
    for (long long t = i; t < 320; t += stride) stats[t] = 0.0;
    for (long long t = i; t < NCHUNKMAX; t += stride) g_scan_state[t] = 0ULL;
    const float2* xf2 = (const float2*)x;
    __half2* xh2 = (__half2*)x16;
    for (long long t = i; t < nh2; t += stride)
        xh2[t] = __float22half2_rn(xf2[t]);
    for (long long t = i; t < 128 * 256; t += stride) {
        int n = (int)(t >> 8), k = (int)(t & 255);
        float v = (k < 128) ? Wrel1[k * 128 + n] : Wroot1[(k - 128) * 128 + n];
        w1hT[t] = __float2half_rn(v);
    }
    for (long long t = i; t < 64 * 128; t += stride) {
        int n = (int)(t >> 7), k = (int)(t & 127);
        float v = (n < 32) ? Wrel2[k * 32 + n] : Wroot2[k * 32 + (n - 32)];
        w2hT[t] = __float2half_rn(v);
    }
    if (blockIdx.x == 0 && threadIdx.x == 0) {
        int n = 2 * E;
        int allzero = 1;
        for (int k = 1; k < 256 && k < n; k += 2) {
            if (ei[k] != 0) { allzero = 0; break; }
        }
        g_is64 = allzero;
    }
}

__device__ __forceinline__ void load_edge(const void* eiv, int E, int e, int& s, int& d) {
    if (g_is64) {
        const long long* p = (const long long*)eiv;
        s = (int)p[e];
        d = (int)p[(size_t)E + e];
    } else {
        const int* p = (const int*)eiv;
        s = p[e];
        d = p[E + e];
    }
}

// ---------------- CSR build ----------------
__global__ void __launch_bounds__(256) hist_kernel(const void* eiv, int E, int* deg) {
    int e = blockIdx.x * 256 + threadIdx.x;
    int stride = gridDim.x * 256;
    for (; e < E; e += stride) {
        int s, d;
        load_edge(eiv, E, e, s, d);
        atomicAdd(&deg[d], 1);
    }
}

// single-pass decoupled-lookback inclusive scan (off[1..N] = prefix sums, off[0]=0)
__global__ void __launch_bounds__(SCHUNK) scan_lookback_kernel(int* off, int N) {
    __shared__ int sh[SCHUNK];
    __shared__ int base_sh;
    int b = blockIdx.x;
    int i = b * SCHUNK + threadIdx.x;
    int v = (i < N) ? off[i] : 0;
    sh[threadIdx.x] = v;
    __syncthreads();
#pragma unroll
    for (int o = 1; o < SCHUNK; o <<= 1) {
        int t = (threadIdx.x >= (unsigned)o) ? sh[threadIdx.x - o] : 0;
        __syncthreads();
        sh[threadIdx.x] += t;
        __syncthreads();
    }
    if (threadIdx.x == 0) {
        unsigned agg = (unsigned)sh[SCHUNK - 1];
        if (b == 0) {
            base_sh = 0;
            __threadfence();
            atomicExch(&g_scan_state[0], (2ULL << 32) | agg);
        } else {
            atomicExch(&g_scan_state[b], (1ULL << 32) | agg);
            int idx = b - 1;
            unsigned run = 0;
            while (true) {
                unsigned long long st = atomicAdd(&g_scan_state[idx], 0ULL);
                unsigned flag = (unsigned)(st >> 32);
                if (flag == 2u) { run += (unsigned)st; break; }
                if (flag == 1u) { run += (unsigned)st; idx--; }
            }
            base_sh = (int)run;
            __threadfence();
            atomicExch(&g_scan_state[b], (2ULL << 32) | (run + agg));
        }
    }
    __syncthreads();
    int base = base_sh;
    if (i < N) off[i + 1] = sh[threadIdx.x] + base;
    if (b == 0 && threadIdx.x == 0) off[0] = 0;
}

// after fill: off[d] = END of bucket d; begin(d) = (d==0) ? 0 : off[d-1]
__global__ void __launch_bounds__(256) fill_kernel(const void* eiv, int E, int* off, int* csrc) {
    int e = blockIdx.x * 256 + threadIdx.x;
    int stride = gridDim.x * 256;
    for (; e < E; e += stride) {
        int s, d;
        load_edge(eiv, E, e, s, d);
        int pos = atomicAdd(&off[d], 1);
        csrc[pos] = s;
    }
}

// ---------------- gather1: 16 lanes/row, 8 halves/lane ----------------
__global__ void __launch_bounds__(256) gather1_kernel(
    const __half* __restrict__ feat, const int* __restrict__ off,
    const int* __restrict__ csrc, __half* __restrict__ out, int N)
{
    int gid = blockIdx.x * 256 + threadIdx.x;
    int w = gid >> 4;
    int j = gid & 15;
    if (w >= N) return;
    int end = __ldg(&off[w]);
    int beg = (w == 0) ? 0 : __ldg(&off[w - 1]);

    float2 acc0 = make_float2(0.f, 0.f), acc1 = acc0, acc2 = acc0, acc3 = acc0;
    const __half* base = feat + j * 8;
    int k = beg;
    for (; k + 2 <= end; k += 2) {
        int s0 = __ldg(&csrc[k]);
        int s1 = __ldg(&csrc[k + 1]);
        uint4 r0 = *(const uint4*)(base + (size_t)s0 * D_IN);
        uint4 r1 = *(const uint4*)(base + (size_t)s1 * D_IN);
        float2 f;
        f = __half22float2(*(__half2*)&r0.x); acc0.x += f.x; acc0.y += f.y;
        f = __half22float2(*(__half2*)&r0.y); acc1.x += f.x; acc1.y += f.y;
        f = __half22float2(*(__half2*)&r0.z); acc2.x += f.x; acc2.y += f.y;
        f = __half22float2(*(__half2*)&r0.w); acc3.x += f.x; acc3.y += f.y;
        f = __half22float2(*(__half2*)&r1.x); acc0.x += f.x; acc0.y += f.y;
        f = __half22float2(*(__half2*)&r1.y); acc1.x += f.x; acc1.y += f.y;
        f = __half22float2(*(__half2*)&r1.z); acc2.x += f.x; acc2.y += f.y;
        f = __half22float2(*(__half2*)&r1.w); acc3.x += f.x; acc3.y += f.y;
    }
    if (k < end) {
        int s0 = __ldg(&csrc[k]);
        uint4 r0 = *(const uint4*)(base + (size_t)s0 * D_IN);
        float2 f;
        f = __half22float2(*(__half2*)&r0.x); acc0.x += f.x; acc0.y += f.y;
        f = __half22float2(*(__half2*)&r0.y); acc1.x += f.x; acc1.y += f.y;
        f = __half22float2(*(__half2*)&r0.z); acc2.x += f.x; acc2.y += f.y;
        f = __half22float2(*(__half2*)&r0.w); acc3.x += f.x; acc3.y += f.y;
    }
    uint4 o;
    *(__half2*)&o.x = __float22half2_rn(acc0);
    *(__half2*)&o.y = __float22half2_rn(acc1);
    *(__half2*)&o.z = __float22half2_rn(acc2);
    *(__half2*)&o.w = __float22half2_rn(acc3);
    *(uint4*)(out + (size_t)w * D_HID + j * 8) = o;
}

// ---------------- gemm1: h1h = [agg1h | x16] @ w1hT' + b (fp16 out); fused BN1 stats ----------------
// software-pipelined: global loads for stage it+1 issued during MMA of stage it.
__global__ void __launch_bounds__(256) gemm1_kernel(
    const __half* __restrict__ Ah, const __half* __restrict__ Axh,
    const __half* __restrict__ w1hT,
    const float* __restrict__ bias, __half* __restrict__ C, int M,
    double* __restrict__ sumd, double* __restrict__ sqd)
{
    constexpr int BM = 128, BN = 128, WN = 64, NT = 8;
    constexpr int KPAD = 8;
    __shared__ __half As[BM][32 + KPAD];
    __shared__ __half BsT[BN][32 + KPAD];
    __shared__ float shs[BN], shq[BN];

    const int tid = threadIdx.x;
    const int lane = tid & 31;
    const int wid = tid >> 5;
    const int warp_m = wid & 3;
    const int warp_n = wid >> 2;
    const int m0 = blockIdx.x * BM;
    const int tg = lane & 3;
    const int gi = lane >> 2;

    if (tid < BN) { shs[tid] = 0.f; shq[tid] = 0.f; }

    // fixed per-thread staging coordinates
    const int rA0 = tid >> 2,            cA0 = (tid & 3) << 3;
    const int rA1 = (tid + 256) >> 2,    cA1 = ((tid + 256) & 3) << 3;

    float acc[2][NT][4];
#pragma unroll
    for (int mt = 0; mt < 2; mt++)
#pragma unroll
        for (int nt = 0; nt < NT; nt++)
#pragma unroll
            for (int r = 0; r < 4; r++) acc[mt][nt][r] = 0.f;

    auto loadStage = [&](int it, uint4& a0, uint4& a1, uint4& b0, uint4& b1) {
        const __half* Asrc = (it < 4) ? Ah : Axh;
        int kloc = (it & 3) * 32;
        int kglob = it * 32;
        a0 = make_uint4(0, 0, 0, 0);
        a1 = make_uint4(0, 0, 0, 0);
        if (m0 + rA0 < M) a0 = *(const uint4*)(Asrc + (size_t)(m0 + rA0) * 128 + kloc + cA0);
        if (m0 + rA1 < M) a1 = *(const uint4*)(Asrc + (size_t)(m0 + rA1) * 128 + kloc + cA1);
        b0 = *(const uint4*)(w1hT + (size_t)rA0 * 256 + kglob + cA0);
        b1 = *(const uint4*)(w1hT + (size_t)rA1 * 256 + kglob + cA1);
    };

    uint4 a0, a1, b0, b1;
    loadStage(0, a0, a1, b0, b1);

    for (int it = 0; it < 8; it++) {
        *(uint4*)&As[rA0][cA0] = a0;
        *(uint4*)&As[rA1][cA1] = a1;
        *(uint4*)&BsT[rA0][cA0] = b0;
        *(uint4*)&BsT[rA1][cA1] = b1;
        __syncthreads();
        uint4 na0, na1, nb0, nb1;
        if (it < 7) loadStage(it + 1, na0, na1, nb0, nb1);

#pragma unroll
        for (int ks = 0; ks < 2; ks++) {
            int k16 = ks * 16;
            unsigned a[2][4];
#pragma unroll
            for (int mt = 0; mt < 2; mt++) {
                int rb = warp_m * 32 + mt * 16;
                a[mt][0] = *(const unsigned*)&As[rb + gi][k16 + 2 * tg];
                a[mt][1] = *(const unsigned*)&As[rb + 8 + gi][k16 + 2 * tg];
                a[mt][2] = *(const unsigned*)&As[rb + gi][k16 + 8 + 2 * tg];
                a[mt][3] = *(const unsigned*)&As[rb + 8 + gi][k16 + 8 + 2 * tg];
            }
            unsigned b[NT][2];
#pragma unroll
            for (int nt = 0; nt < NT; nt++) {
                int col = warp_n * WN + nt * 8 + gi;
                b[nt][0] = *(const unsigned*)&BsT[col][k16 + 2 * tg];
                b[nt][1] = *(const unsigned*)&BsT[col][k16 + 8 + 2 * tg];
            }
#pragma unroll
            for (int mt = 0; mt < 2; mt++)
#pragma unroll
                for (int nt = 0; nt < NT; nt++)
                    mma_f16(acc[mt][nt], a[mt], b[nt]);
        }
        __syncthreads();
        if (it < 7) { a0 = na0; a1 = na1; b0 = nb0; b1 = nb1; }
    }

    // epilogue: bias, fp16 store, fused column stats
#pragma unroll
    for (int nt = 0; nt < NT; nt++) {
        int col = warp_n * WN + nt * 8 + tg * 2;
        float bx = __ldg(&bias[col]);
        float by = __ldg(&bias[col + 1]);
        float s0 = 0.f, s1 = 0.f, q0 = 0.f, q1 = 0.f;
#pragma unroll
        for (int mt = 0; mt < 2; mt++) {
            int r0 = m0 + warp_m * 32 + mt * 16 + gi;
            int r1 = r0 + 8;
            float vx = acc[mt][nt][0] + bx, vy = acc[mt][nt][1] + by;
            float wx = acc[mt][nt][2] + bx, wy = acc[mt][nt][3] + by;
            if (r0 < M) {
                *(__half2*)(C + (size_t)r0 * BN + col) = __floats2half2_rn(vx, vy);
                s0 += vx; q0 += vx * vx; s1 += vy; q1 += vy * vy;
            }
            if (r1 < M) {
                *(__half2*)(C + (size_t)r1 * BN + col) = __floats2half2_rn(wx, wy);
                s0 += wx; q0 += wx * wx; s1 += wy; q1 += wy * wy;
            }
        }
#pragma unroll
        for (int msk = 4; msk < 32; msk <<= 1) {
            s0 += __shfl_xor_sync(0xffffffffu, s0, msk);
            s1 += __shfl_xor_sync(0xffffffffu, s1, msk);
            q0 += __shfl_xor_sync(0xffffffffu, q0, msk);
            q1 += __shfl_xor_sync(0xffffffffu, q1, msk);
        }
        if (gi == 0) {
            atomicAdd(&shs[col], s0);
            atomicAdd(&shs[col + 1], s1);
            atomicAdd(&shq[col], q0);
            atomicAdd(&shq[col + 1], q1);
        }
    }
    __syncthreads();
    if (tid < BN) {
        atomicAdd(&sumd[tid], (double)shs[tid]);
        atomicAdd(&sqd[tid], (double)shq[tid]);
    }
}

// ---------------- gemm2: [t16 | r2] = relu(bn(h1h)) @ w2hT' ----------------
__global__ void __launch_bounds__(256) gemm2_kernel(
    const __half* __restrict__ A, const __half* __restrict__ w2hT,
    float* __restrict__ tr, __half* __restrict__ t16, int M,
    const float* __restrict__ ascale, const float* __restrict__ ashift)
{
    constexpr int BM = 128, BK = 32, BN = 64, WN = 32, NT = 4;
    constexpr int KPAD = 8;
    __shared__ __half As[BM][BK + KPAD];
    __shared__ __half BsT[BN][BK + KPAD];

    const int tid = threadIdx.x;
    const int lane = tid & 31;
    const int wid = tid >> 5;
    const int warp_m = wid & 3;
    const int warp_n = wid >> 2;
    const int m0 = blockIdx.x * BM;
    const int tg = lane & 3;
    const int gi = lane >> 2;

    float acc[2][NT][4];
#pragma unroll
    for (int mt = 0; mt < 2; mt++)
#pragma unroll
        for (int nt = 0; nt < NT; nt++)
#pragma unroll
            for (int r = 0; r < 4; r++) acc[mt][nt][r] = 0.f;

    for (int kc = 0; kc < D_HID; kc += BK) {
        // stage A from fp16 h1 with BN+relu
#pragma unroll
        for (int t = 0; t < 2; t++) {
            int v = tid + t * 256;
            int row = v >> 2;
            int c8 = (v & 3) << 3;
            uint4 rw = make_uint4(0, 0, 0, 0);
            if (m0 + row < M)
                rw = *(const uint4*)(A + (size_t)(m0 + row) * D_HID + kc + c8);
            int kg = kc + c8;
            uint4 outw;
            const unsigned* pin = (const unsigned*)&rw;
            unsigned* pout = (unsigned*)&outw;
#pragma unroll
            for (int q = 0; q < 4; q++) {
                float2 f = __half22float2(*(const __half2*)&pin[q]);
                int k0 = kg + q * 2;
                f.x = fmaxf(fmaf(f.x, __ldg(&ascale[k0]), __ldg(&ashift[k0])), 0.f);
                f.y = fmaxf(fmaf(f.y, __ldg(&ascale[k0 + 1]), __ldg(&ashift[k0 + 1])), 0.f);
                *(__half2*)&pout[q] = __float22half2_rn(f);
            }
            *(uint4*)&As[row][c8] = outw;
        }
        // stage B transposed
        {
            int n = tid >> 2;
            int c8 = (tid & 3) << 3;
            uint4 rw = *(const uint4*)(w2hT + (size_t)n * 128 + kc + c8);
            *(uint4*)&BsT[n][c8] = rw;
        }
        __syncthreads();

#pragma unroll
        for (int ks = 0; ks < 2; ks++) {
            int k16 = ks * 16;
            unsigned a[2][4];
#pragma unroll
            for (int mt = 0; mt < 2; mt++) {
                int rb = warp_m * 32 + mt * 16;
                a[mt][0] = *(const unsigned*)&As[rb + gi][k16 + 2 * tg];
                a[mt][1] = *(const unsigned*)&As[rb + 8 + gi][k16 + 2 * tg];
                a[mt][2] = *(const unsigned*)&As[rb + gi][k16 + 8 + 2 * tg];
                a[mt][3] = *(const unsigned*)&As[rb + 8 + gi][k16 + 8 + 2 * tg];
            }
            unsigned b[NT][2];
#pragma unroll
            for (int nt = 0; nt < NT; nt++) {
                int col = warp_n * WN + nt * 8 + gi;
                b[nt][0] = *(const unsigned*)&BsT[col][k16 + 2 * tg];
                b[nt][1] = *(const unsigned*)&BsT[col][k16 + 8 + 2 * tg];
            }
#pragma unroll
            for (int mt = 0; mt < 2; mt++)
#pragma unroll
                for (int nt = 0; nt < NT; nt++)
                    mma_f16(acc[mt][nt], a[mt], b[nt]);
        }
        __syncthreads();
    }

#pragma unroll
    for (int mt = 0; mt < 2; mt++) {
        int r0 = m0 + warp_m * 32 + mt * 16 + gi;
        int r1 = r0 + 8;
#pragma unroll
        for (int nt = 0; nt < NT; nt++) {
            int col = warp_n * WN + nt * 8 + tg * 2;
            if (warp_n == 0) {
                if (r0 < M)
                    *(__half2*)(t16 + (size_t)r0 * 32 + col) =
                        __floats2half2_rn(acc[mt][nt][0], acc[mt][nt][1]);
                if (r1 < M)
                    *(__half2*)(t16 + (size_t)r1 * 32 + col) =
                        __floats2half2_rn(acc[mt][nt][2], acc[mt][nt][3]);
            } else {
                if (r0 < M)
                    *(float2*)(tr + (size_t)r0 * 64 + col) =
                        make_float2(acc[mt][nt][0], acc[mt][nt][1]);
                if (r1 < M)
                    *(float2*)(tr + (size_t)r1 * 64 + col) =
                        make_float2(acc[mt][nt][2], acc[mt][nt][3]);
            }
        }
    }
}

// ---------------- gather2 fused: agg2 = gather(t16) + r2 + bias; BN2 stats ----------------
__global__ void __launch_bounds__(256) gather2_fused_kernel(
    const __half* __restrict__ feat, const int* __restrict__ off,
    const int* __restrict__ csrc, const float* __restrict__ tr,
    const float* __restrict__ bias, float* __restrict__ out, int N,
    double* __restrict__ sumd, double* __restrict__ sqd)
{
    __shared__ float shs[32], shq[32];
    int tid = threadIdx.x;
    if (tid < 32) { shs[tid] = 0.f; shq[tid] = 0.f; }
    __syncthreads();

    int gid = blockIdx.x * 256 + tid;
    int w = gid >> 2;
    int j = gid & 3;
    bool valid = (w < N);

    float v[8];
#pragma unroll
    for (int q = 0; q < 8; q++) v[q] = 0.f;

    if (valid) {
        int end = __ldg(&off[w]);
        int beg = (w == 0) ? 0 : __ldg(&off[w - 1]);
        const __half* base = feat + j * 8;
        for (int k = beg; k < end; k++) {
            int s0 = __ldg(&csrc[k]);
            uint4 r0 = *(const uint4*)(base + (size_t)s0 * 32);
            float2 f;
            f = __half22float2(*(__half2*)&r0.x); v[0] += f.x; v[1] += f.y;
            f = __half22float2(*(__half2*)&r0.y); v[2] += f.x; v[3] += f.y;
            f = __half22float2(*(__half2*)&r0.z); v[4] += f.x; v[5] += f.y;
            f = __half22float2(*(__half2*)&r0.w); v[6] += f.x; v[7] += f.y;
        }
        const float* rp = tr + (size_t)w * 64 + 32 + j * 8;
        float4 ra = *(const float4*)(rp + 0);
        float4 rb = *(const float4*)(rp + 4);
        const float* bp = bias + j * 8;
        v[0] += ra.x + __ldg(bp + 0); v[1] += ra.y + __ldg(bp + 1);
        v[2] += ra.z + __ldg(bp + 2); v[3] += ra.w + __ldg(bp + 3);
        v[4] += rb.x + __ldg(bp + 4); v[5] += rb.y + __ldg(bp + 5);
        v[6] += rb.z + __ldg(bp + 6); v[7] += rb.w + __ldg(bp + 7);
        float* op = out + (size_t)w * D_OUT + j * 8;
        *(float4*)(op + 0) = make_float4(v[0], v[1], v[2], v[3]);
        *(float4*)(op + 4) = make_float4(v[4], v[5], v[6], v[7]);
    }

    float s[8], q[8];
#pragma unroll
    for (int t = 0; t < 8; t++) {
        s[t] = valid ? v[t] : 0.f;
        q[t] = valid ? v[t] * v[t] : 0.f;
    }
#pragma unroll
    for (int msk = 4; msk < 32; msk <<= 1)
#pragma unroll
        for (int t = 0; t < 8; t++) {
            s[t] += __shfl_xor_sync(0xffffffffu, s[t], msk);
            q[t] += __shfl_xor_sync(0xffffffffu, q[t], msk);
        }
    if ((tid & 31) < 4) {
#pragma unroll
        for (int t = 0; t < 8; t++) {
            atomicAdd(&shs[j * 8 + t], s[t]);
            atomicAdd(&shq[j * 8 + t], q[t]);
        }
    }
    __syncthreads();
    if (tid < 32) {
        atomicAdd(&sumd[tid], (double)shs[tid]);
        atomicAdd(&sqd[tid], (double)shq[tid]);
    }
}

// ---------------- BN finalize + final normalize/relu ----------------
__global__ void bn_finalize_kernel(
    const double* __restrict__ sum, const double* __restrict__ sq,
    const float* __restrict__ gamma, const float* __restrict__ beta,
    float* __restrict__ scale, float* __restrict__ shift, float invM)
{
    int c = threadIdx.x;
    double mu = sum[c] * (double)invM;
    double var = sq[c] * (double)invM - mu * mu;
    float s = gamma[c] * rsqrtf((float)var + 1e-5f);
    scale[c] = s;
    shift[c] = beta[c] - (float)mu * s;
}

__global__ void __launch_bounds__(256) bn_relu4_kernel(
    const float4* __restrict__ in, float4* __restrict__ out, long long n4,
    const float* __restrict__ scale, const float* __restrict__ shift)
{
    long long i = (long long)blockIdx.x * blockDim.x + threadIdx.x;
    long long stride = (long long)gridDim.x * blockDim.x;
    for (; i < n4; i += stride) {
        int c = (int)((i << 2) & 31);
        float4 v = in[i];
        v.x = fmaxf(fmaf(v.x, __ldg(&scale[c + 0]), __ldg(&shift[c + 0])), 0.f);
        v.y = fmaxf(fmaf(v.y, __ldg(&scale[c + 1]), __ldg(&shift[c + 1])), 0.f);
        v.z = fmaxf(fmaf(v.z, __ldg(&scale[c + 2]), __ldg(&shift[c + 2])), 0.f);
        v.w = fmaxf(fmaf(v.w, __ldg(&scale[c + 3]), __ldg(&shift[c + 3])), 0.f);
        out[i] = v;
    }
}

static inline int ceil_div_i(int a, int b) { return (a + b - 1) / b; }

// ---------------- launch ----------------
extern "C" void kernel_launch(void* const* d_in, const int* in_sizes, int n_in,
                              void* d_out, int out_size)
{
    const float* x      = (const float*)d_in[0];
    const void*  ei     = d_in[1];
    const float* Wrel1  = (const float*)d_in[2];
    const float* brel1  = (const float*)d_in[3];
    const float* Wroot1 = (const float*)d_in[4];
    const float* gamma1 = (const float*)d_in[5];
    const float* beta1  = (const float*)d_in[6];
    const float* Wrel2  = (const float*)d_in[7];
    const float* brel2  = (const float*)d_in[8];
    const float* Wroot2 = (const float*)d_in[9];
    const float* gamma2 = (const float*)d_in[10];
    const float* beta2  = (const float*)d_in[11];

    const int N = in_sizes[0] / D_IN;
    const int E = in_sizes[1] / 2;

    float *tr, *agg2, *ss;
    __half *x16, *agg1h, *h1h, *t16, *w1hT, *w2hT;
    double* stats;
    int *off, *csrc;
    cudaGetSymbolAddress((void**)&x16, g_x16);
    cudaGetSymbolAddress((void**)&agg1h, g_agg1h);
    cudaGetSymbolAddress((void**)&h1h, g_h1h);
    cudaGetSymbolAddress((void**)&tr, g_tr);
    cudaGetSymbolAddress((void**)&t16, g_t16);
    cudaGetSymbolAddress((void**)&agg2, g_agg2);
    cudaGetSymbolAddress((void**)&stats, g_stats);
    cudaGetSymbolAddress((void**)&ss, g_ss);
    cudaGetSymbolAddress((void**)&w1hT, g_w1hT);
    cudaGetSymbolAddress((void**)&w2hT, g_w2hT);
    cudaGetSymbolAddress((void**)&off, g_off);
    cudaGetSymbolAddress((void**)&csrc, g_csrc);

    const int nchunks = ceil_div_i(N, SCHUNK);
    const int eblocks = ceil_div_i(E, 256);

    init_kernel<<<2048, 256>>>((const int*)ei, E, off, N, stats, x, x16,
                               (long long)N * D_IN / 2,
                               Wrel1, Wroot1, Wrel2, Wroot2, w1hT, w2hT);
    hist_kernel<<<eblocks, 256>>>(ei, E, off);
    scan_lookback_kernel<<<nchunks, SCHUNK>>>(off, N);
    fill_kernel<<<eblocks, 256>>>(ei, E, off, csrc);

    gather1_kernel<<<ceil_div_i(N * 16, 256), 256>>>(x16, off, csrc, agg1h, N);
    gemm1_kernel<<<ceil_div_i(N, 128), 256>>>(
        agg1h, x16, w1hT, brel1, h1h, N, stats, stats + 128);
    bn_finalize_kernel<<<1, 128>>>(stats, stats + 128, gamma1, beta1, ss, ss + 128,
                                   1.0f / (float)N);

    gemm2_kernel<<<ceil_div_i(N, 128), 256>>>(h1h, w2hT, tr, t16, N, ss, ss + 128);
    gather2_fused_kernel<<<ceil_div_i(N * 4, 256), 256>>>(
        t16, off, csrc, tr, brel2, agg2, N, stats + 256, stats + 288);

    bn_finalize_kernel<<<1, 32>>>(stats + 256, stats + 288, gamma2, beta2,
                                  ss + 256, ss + 288, 1.0f / (float)N);
    bn_relu4_kernel<<<1024, 256>>>((const float4*)agg2, (float4*)d_out,
                                   (long long)N * D_OUT / 4, ss + 256, ss + 288);
}

// round 10
// speedup vs baseline: 4.5475x; 1.0040x over previous
#include <cuda_runtime.h>
#include <cuda_fp16.h>
#include <cstddef>

#define D_IN  128
#define D_HID 128
#define D_OUT 32
#define NMAX  100000
#define EMAX  1601000
#define SCHUNK 1024
#define NCHUNKMAX 128

// ---------------- static device scratch (no runtime allocation) ----------------
__device__ __half g_x16 [(size_t)NMAX * D_IN];
__device__ __half g_agg1h[(size_t)NMAX * D_HID];
__device__ __half g_h1h [(size_t)NMAX * D_HID];   // pre-BN h1 (fp16)
__device__ __half g_r2h [(size_t)NMAX * 32];      // r2 = relu(bn(h1))@W_root2 (fp16)
__device__ __half g_t16 [(size_t)NMAX * 32];      // t  = relu(bn(h1))@W_rel2  (fp16)
__device__ float  g_agg2[(size_t)NMAX * D_OUT];
__device__ double g_stats[320];
__device__ __half g_w1hT [128 * 256];
__device__ __half g_w2hT [64 * 128];
__device__ int    g_off[NMAX + 1];
__device__ unsigned long long g_scan_state[NCHUNKMAX];
__device__ int    g_csrc[EMAX];
__device__ int    g_is64;

// ---------------- fp16 MMA helper ----------------
__device__ __forceinline__ void mma_f16(float c[4], const unsigned a[4], const unsigned b[2]) {
    asm volatile(
        "mma.sync.aligned.m16n8k16.row.col.f32.f16.f16.f32 "
        "{%0,%1,%2,%3}, {%4,%5,%6,%7}, {%8,%9}, {%0,%1,%2,%3};"
        : "+f"(c[0]), "+f"(c[1]), "+f"(c[2]), "+f"(c[3])
        : "r"(a[0]), "r"(a[1]), "r"(a[2]), "r"(a[3]), "r"(b[0]), "r"(b[1]));
}

// ---------------- main chain #0: zero off + scan_state, detect dtype ----------------
__global__ void __launch_bounds__(256) zero_off_kernel(const int* ei, int E, int* off, int N) {
    int i = blockIdx.x * 256 + threadIdx.x;
    int stride = gridDim.x * 256;
    for (int t = i; t <= N; t += stride) off[t] = 0;
    for (int t = i; t < NCHUNKMAX; t += stride) g_scan_state[t] = 0ULL;
    if (blockIdx.x == 0 && threadIdx.x == 0) {
        int n = 2 * E;
        int allzero = 1;
        for (int k = 1; k < 256 && k < n; k += 2) {
            if (ei[k] != 0) { allzero = 0; break; }
        }
        g_is64 = allzero;
    }
}

// ---------------- side chain: stats zero + x->fp16 + weight prep ----------------
__global__ void __launch_bounds__(256) init_kernel(
    double* stats,
    const float* __restrict__ x, __half* __restrict__ x16, long long nh2,
    const float* __restrict__ Wrel1, const float* __restrict__ Wroot1,
    const float* __restrict__ Wrel2, const float* __restrict__ Wroot2,
    __half* __restrict__ w1hT, __half* __restrict__ w2hT)
{
    long long i = (long long)blockIdx.x * 256 + threadIdx.x;
    long long stride = (long long)gridDim.x * 256;
    for (long long t = i; t < 320; t += stride) stats[t] = 0.0;
    const float2* xf2 = (const float2*)x;
    __half2* xh2 = (__half2*)x16;
    for (long long t = i; t < nh2; t += stride)
        xh2[t] = __float22half2_rn(xf2[t]);
    for (long long t = i; t < 128 * 256; t += stride) {
        int n = (int)(t >> 8), k = (int)(t & 255);
        float v = (k < 128) ? Wrel1[k * 128 + n] : Wroot1[(k - 128) * 128 + n];
        w1hT[t] = __float2half_rn(v);
    }
    for (long long t = i; t < 64 * 128; t += stride) {
        int n = (int)(t >> 7), k = (int)(t & 127);
        float v = (n < 32) ? Wrel2[k * 32 + n] : Wroot2[k * 32 + (n - 32)];
        w2hT[t] = __float2half_rn(v);
    }
}

__device__ __forceinline__ void load_edge(const void* eiv, int E, int e, int& s, int& d) {
    if (g_is64) {
        const long long* p = (const long long*)eiv;
        s = (int)p[e];
        d = (int)p[(size_t)E + e];
    } else {
        const int* p = (const int*)eiv;
        s = p[e];
        d = p[E + e];
    }
}

// ---------------- CSR build ----------------
// histogram: only dst needed
__global__ void __launch_bounds__(256) hist_kernel(const void* eiv, int E, int* deg) {
    int e = blockIdx.x * 256 + threadIdx.x;
    int stride = gridDim.x * 256;
    const int is64 = g_is64;
    for (; e < E; e += stride) {
        int d;
        if (is64) d = (int)((const long long*)eiv)[(size_t)E + e];
        else      d = ((const int*)eiv)[E + e];
        atomicAdd(&deg[d], 1);
    }
}

// single-pass decoupled-lookback inclusive scan (off[1..N] = prefix sums, off[0]=0)
__global__ void __launch_bounds__(SCHUNK) scan_lookback_kernel(int* off, int N) {
    __shared__ int sh[SCHUNK];
    __shared__ int base_sh;
    int b = blockIdx.x;
    int i = b * SCHUNK + threadIdx.x;
    int v = (i < N) ? off[i] : 0;
    sh[threadIdx.x] = v;
    __syncthreads();
#pragma unroll
    for (int o = 1; o < SCHUNK; o <<= 1) {
        int t = (threadIdx.x >= (unsigned)o) ? sh[threadIdx.x - o] : 0;
        __syncthreads();
        sh[threadIdx.x] += t;
        __syncthreads();
    }
    if (threadIdx.x == 0) {
        unsigned agg = (unsigned)sh[SCHUNK - 1];
        if (b == 0) {
            base_sh = 0;
            __threadfence();
            atomicExch(&g_scan_state[0], (2ULL << 32) | agg);
        } else {
            atomicExch(&g_scan_state[b], (1ULL << 32) | agg);
            int idx = b - 1;
            unsigned run = 0;
            while (true) {
                unsigned long long st = atomicAdd(&g_scan_state[idx], 0ULL);
                unsigned flag = (unsigned)(st >> 32);
                if (flag == 2u) { run += (unsigned)st; break; }
                if (flag == 1u) { run += (unsigned)st; idx--; }
            }
            base_sh = (int)run;
            __threadfence();
            atomicExch(&g_scan_state[b], (2ULL << 32) | (run + agg));
        }
    }
    __syncthreads();
    int base = base_sh;
    if (i < N) off[i + 1] = sh[threadIdx.x] + base;
    if (b == 0 && threadIdx.x == 0) off[0] = 0;
}

// after fill: off[d] = END of bucket d; begin(d) = (d==0) ? 0 : off[d-1]
__global__ void __launch_bounds__(256) fill_kernel(const void* eiv, int E, int* off, int* csrc) {
    int e = blockIdx.x * 256 + threadIdx.x;
    int stride = gridDim.x * 256;
    for (; e < E; e += stride) {
        int s, d;
        load_edge(eiv, E, e, s, d);
        int pos = atomicAdd(&off[d], 1);
        csrc[pos] = s;
    }
}

// ---------------- gather1: 16 lanes/row, 8 halves/lane ----------------
__global__ void __launch_bounds__(256) gather1_kernel(
    const __half* __restrict__ feat, const int* __restrict__ off,
    const int* __restrict__ csrc, __half* __restrict__ out, int N)
{
    int gid = blockIdx.x * 256 + threadIdx.x;
    int w = gid >> 4;
    int j = gid & 15;
    if (w >= N) return;
    int end = __ldg(&off[w]);
    int beg = (w == 0) ? 0 : __ldg(&off[w - 1]);

    float2 acc0 = make_float2(0.f, 0.f), acc1 = acc0, acc2 = acc0, acc3 = acc0;
    const __half* base = feat + j * 8;
    int k = beg;
    for (; k + 2 <= end; k += 2) {
        int s0 = __ldg(&csrc[k]);
        int s1 = __ldg(&csrc[k + 1]);
        uint4 r0 = *(const uint4*)(base + (size_t)s0 * D_IN);
        uint4 r1 = *(const uint4*)(base + (size_t)s1 * D_IN);
        float2 f;
        f = __half22float2(*(__half2*)&r0.x); acc0.x += f.x; acc0.y += f.y;
        f = __half22float2(*(__half2*)&r0.y); acc1.x += f.x; acc1.y += f.y;
        f = __half22float2(*(__half2*)&r0.z); acc2.x += f.x; acc2.y += f.y;
        f = __half22float2(*(__half2*)&r0.w); acc3.x += f.x; acc3.y += f.y;
        f = __half22float2(*(__half2*)&r1.x); acc0.x += f.x; acc0.y += f.y;
        f = __half22float2(*(__half2*)&r1.y); acc1.x += f.x; acc1.y += f.y;
        f = __half22float2(*(__half2*)&r1.z); acc2.x += f.x; acc2.y += f.y;
        f = __half22float2(*(__half2*)&r1.w); acc3.x += f.x; acc3.y += f.y;
    }
    if (k < end) {
        int s0 = __ldg(&csrc[k]);
        uint4 r0 = *(const uint4*)(base + (size_t)s0 * D_IN);
        float2 f;
        f = __half22float2(*(__half2*)&r0.x); acc0.x += f.x; acc0.y += f.y;
        f = __half22float2(*(__half2*)&r0.y); acc1.x += f.x; acc1.y += f.y;
        f = __half22float2(*(__half2*)&r0.z); acc2.x += f.x; acc2.y += f.y;
        f = __half22float2(*(__half2*)&r0.w); acc3.x += f.x; acc3.y += f.y;
    }
    uint4 o;
    *(__half2*)&o.x = __float22half2_rn(acc0);
    *(__half2*)&o.y = __float22half2_rn(acc1);
    *(__half2*)&o.z = __float22half2_rn(acc2);
    *(__half2*)&o.w = __float22half2_rn(acc3);
    *(uint4*)(out + (size_t)w * D_HID + j * 8) = o;
}

// ---------------- gemm1: h1h = [agg1h | x16] @ w1hT' + b (fp16 out); fused BN1 stats ----------------
__global__ void __launch_bounds__(256) gemm1_kernel(
    const __half* __restrict__ Ah, const __half* __restrict__ Axh,
    const __half* __restrict__ w1hT,
    const float* __restrict__ bias, __half* __restrict__ C, int M,
    double* __restrict__ sumd, double* __restrict__ sqd)
{
    constexpr int BM = 128, BN = 128, WN = 64, NT = 8;
    constexpr int KPAD = 8;
    __shared__ __half As[BM][32 + KPAD];
    __shared__ __half BsT[BN][32 + KPAD];
    __shared__ float shs[BN], shq[BN];

    const int tid = threadIdx.x;
    const int lane = tid & 31;
    const int wid = tid >> 5;
    const int warp_m = wid & 3;
    const int warp_n = wid >> 2;
    const int m0 = blockIdx.x * BM;
    const int tg = lane & 3;
    const int gi = lane >> 2;

    if (tid < BN) { shs[tid] = 0.f; shq[tid] = 0.f; }

    const int rA0 = tid >> 2,            cA0 = (tid & 3) << 3;
    const int rA1 = (tid + 256) >> 2,    cA1 = ((tid + 256) & 3) << 3;

    float acc[2][NT][4];
#pragma unroll
    for (int mt = 0; mt < 2; mt++)
#pragma unroll
        for (int nt = 0; nt < NT; nt++)
#pragma unroll
            for (int r = 0; r < 4; r++) acc[mt][nt][r] = 0.f;

    auto loadStage = [&](int it, uint4& a0, uint4& a1, uint4& b0, uint4& b1) {
        const __half* Asrc = (it < 4) ? Ah : Axh;
        int kloc = (it & 3) * 32;
        int kglob = it * 32;
        a0 = make_uint4(0, 0, 0, 0);
        a1 = make_uint4(0, 0, 0, 0);
        if (m0 + rA0 < M) a0 = *(const uint4*)(Asrc + (size_t)(m0 + rA0) * 128 + kloc + cA0);
        if (m0 + rA1 < M) a1 = *(const uint4*)(Asrc + (size_t)(m0 + rA1) * 128 + kloc + cA1);
        b0 = *(const uint4*)(w1hT + (size_t)rA0 * 256 + kglob + cA0);
        b1 = *(const uint4*)(w1hT + (size_t)rA1 * 256 + kglob + cA1);
    };

    uint4 a0, a1, b0, b1;
    loadStage(0, a0, a1, b0, b1);

    for (int it = 0; it < 8; it++) {
        *(uint4*)&As[rA0][cA0] = a0;
        *(uint4*)&As[rA1][cA1] = a1;
        *(uint4*)&BsT[rA0][cA0] = b0;
        *(uint4*)&BsT[rA1][cA1] = b1;
        __syncthreads();
        uint4 na0, na1, nb0, nb1;
        if (it < 7) loadStage(it + 1, na0, na1, nb0, nb1);

#pragma unroll
        for (int ks = 0; ks < 2; ks++) {
            int k16 = ks * 16;
            unsigned a[2][4];
#pragma unroll
            for (int mt = 0; mt < 2; mt++) {
                int rb = warp_m * 32 + mt * 16;
                a[mt][0] = *(const unsigned*)&As[rb + gi][k16 + 2 * tg];
                a[mt][1] = *(const unsigned*)&As[rb + 8 + gi][k16 + 2 * tg];
                a[mt][2] = *(const unsigned*)&As[rb + gi][k16 + 8 + 2 * tg];
                a[mt][3] = *(const unsigned*)&As[rb + 8 + gi][k16 + 8 + 2 * tg];
            }
            unsigned b[NT][2];
#pragma unroll
            for (int nt = 0; nt < NT; nt++) {
                int col = warp_n * WN + nt * 8 + gi;
                b[nt][0] = *(const unsigned*)&BsT[col][k16 + 2 * tg];
                b[nt][1] = *(const unsigned*)&BsT[col][k16 + 8 + 2 * tg];
            }
#pragma unroll
            for (int mt = 0; mt < 2; mt++)
#pragma unroll
                for (int nt = 0; nt < NT; nt++)
                    mma_f16(acc[mt][nt], a[mt], b[nt]);
        }
        __syncthreads();
        if (it < 7) { a0 = na0; a1 = na1; b0 = nb0; b1 = nb1; }
    }

#pragma unroll
    for (int nt = 0; nt < NT; nt++) {
        int col = warp_n * WN + nt * 8 + tg * 2;
        float bx = __ldg(&bias[col]);
        float by = __ldg(&bias[col + 1]);
        float s0 = 0.f, s1 = 0.f, q0 = 0.f, q1 = 0.f;
#pragma unroll
        for (int mt = 0; mt < 2; mt++) {
            int r0 = m0 + warp_m * 32 + mt * 16 + gi;
            int r1 = r0 + 8;
            float vx = acc[mt][nt][0] + bx, vy = acc[mt][nt][1] + by;
            float wx = acc[mt][nt][2] + bx, wy = acc[mt][nt][3] + by;
            if (r0 < M) {
                *(__half2*)(C + (size_t)r0 * BN + col) = __floats2half2_rn(vx, vy);
                s0 += vx; q0 += vx * vx; s1 += vy; q1 += vy * vy;
            }
            if (r1 < M) {
                *(__half2*)(C + (size_t)r1 * BN + col) = __floats2half2_rn(wx, wy);
                s0 += wx; q0 += wx * wx; s1 += wy; q1 += wy * wy;
            }
        }
#pragma unroll
        for (int msk = 4; msk < 32; msk <<= 1) {
            s0 += __shfl_xor_sync(0xffffffffu, s0, msk);
            s1 += __shfl_xor_sync(0xffffffffu, s1, msk);
            q0 += __shfl_xor_sync(0xffffffffu, q0, msk);
            q1 += __shfl_xor_sync(0xffffffffu, q1, msk);
        }
        if (gi == 0) {
            atomicAdd(&shs[col], s0);
            atomicAdd(&shs[col + 1], s1);
            atomicAdd(&shq[col], q0);
            atomicAdd(&shq[col + 1], q1);
        }
    }
    __syncthreads();
    if (tid < BN) {
        atomicAdd(&sumd[tid], (double)shs[tid]);
        atomicAdd(&sqd[tid], (double)shq[tid]);
    }
}

// ---------------- gemm2: [t16 | r2h] = relu(bn(h1h)) @ w2hT'; BN coeffs computed in-block ----------------
__global__ void __launch_bounds__(256) gemm2_kernel(
    const __half* __restrict__ A, const __half* __restrict__ w2hT,
    __half* __restrict__ r2h, __half* __restrict__ t16, int M,
    const double* __restrict__ stats, const float* __restrict__ gamma,
    const float* __restrict__ beta, float invM)
{
    constexpr int BM = 128, BK = 32, BN = 64, WN = 32, NT = 4;
    constexpr int KPAD = 8;
    __shared__ __half As[BM][BK + KPAD];
    __shared__ __half BsT[BN][BK + KPAD];
    __shared__ float sscale[128], sshift[128];

    const int tid = threadIdx.x;
    const int lane = tid & 31;
    const int wid = tid >> 5;
    const int warp_m = wid & 3;
    const int warp_n = wid >> 2;
    const int m0 = blockIdx.x * BM;
    const int tg = lane & 3;
    const int gi = lane >> 2;

    // per-block BN1 coefficient computation (from global double stats)
    if (tid < 128) {
        double mu = stats[tid] * (double)invM;
        double var = stats[128 + tid] * (double)invM - mu * mu;
        float s = gamma[tid] * rsqrtf((float)var + 1e-5f);
        sscale[tid] = s;
        sshift[tid] = beta[tid] - (float)mu * s;
    }
    __syncthreads();

    float acc[2][NT][4];
#pragma unroll
    for (int mt = 0; mt < 2; mt++)
#pragma unroll
        for (int nt = 0; nt < NT; nt++)
#pragma unroll
            for (int r = 0; r < 4; r++) acc[mt][nt][r] = 0.f;

    for (int kc = 0; kc < D_HID; kc += BK) {
#pragma unroll
        for (int t = 0; t < 2; t++) {
            int v = tid + t * 256;
            int row = v >> 2;
            int c8 = (v & 3) << 3;
            uint4 rw = make_uint4(0, 0, 0, 0);
            if (m0 + row < M)
                rw = *(const uint4*)(A + (size_t)(m0 + row) * D_HID + kc + c8);
            int kg = kc + c8;
            uint4 outw;
            const unsigned* pin = (const unsigned*)&rw;
            unsigned* pout = (unsigned*)&outw;
#pragma unroll
            for (int q = 0; q < 4; q++) {
                float2 f = __half22float2(*(const __half2*)&pin[q]);
                int k0 = kg + q * 2;
                f.x = fmaxf(fmaf(f.x, sscale[k0], sshift[k0]), 0.f);
                f.y = fmaxf(fmaf(f.y, sscale[k0 + 1], sshift[k0 + 1]), 0.f);
                *(__half2*)&pout[q] = __float22half2_rn(f);
            }
            *(uint4*)&As[row][c8] = outw;
        }
        {
            int n = tid >> 2;
            int c8 = (tid & 3) << 3;
            uint4 rw = *(const uint4*)(w2hT + (size_t)n * 128 + kc + c8);
            *(uint4*)&BsT[n][c8] = rw;
        }
        __syncthreads();

#pragma unroll
        for (int ks = 0; ks < 2; ks++) {
            int k16 = ks * 16;
            unsigned a[2][4];
#pragma unroll
            for (int mt = 0; mt < 2; mt++) {
                int rb = warp_m * 32 + mt * 16;
                a[mt][0] = *(const unsigned*)&As[rb + gi][k16 + 2 * tg];
                a[mt][1] = *(const unsigned*)&As[rb + 8 + gi][k16 + 2 * tg];
                a[mt][2] = *(const unsigned*)&As[rb + gi][k16 + 8 + 2 * tg];
                a[mt][3] = *(const unsigned*)&As[rb + 8 + gi][k16 + 8 + 2 * tg];
            }
            unsigned b[NT][2];
#pragma unroll
            for (int nt = 0; nt < NT; nt++) {
                int col = warp_n * WN + nt * 8 + gi;
                b[nt][0] = *(const unsigned*)&BsT[col][k16 + 2 * tg];
                b[nt][1] = *(const unsigned*)&BsT[col][k16 + 8 + 2 * tg];
            }
#pragma unroll
            for (int mt = 0; mt < 2; mt++)
#pragma unroll
                for (int nt = 0; nt < NT; nt++)
                    mma_f16(acc[mt][nt], a[mt], b[nt]);
        }
        __syncthreads();
    }

#pragma unroll
    for (int mt = 0; mt < 2; mt++) {
        int r0 = m0 + warp_m * 32 + mt * 16 + gi;
        int r1 = r0 + 8;
#pragma unroll
        for (int nt = 0; nt < NT; nt++) {
            int col = warp_n * WN + nt * 8 + tg * 2;
            __half* dst = (warp_n == 0) ? t16 : r2h;
            int c = (warp_n == 0) ? col : (col - 32);
            if (r0 < M)
                *(__half2*)(dst + (size_t)r0 * 32 + c) =
                    __floats2half2_rn(acc[mt][nt][0], acc[mt][nt][1]);
            if (r1 < M)
                *(__half2*)(dst + (size_t)r1 * 32 + c) =
                    __floats2half2_rn(acc[mt][nt][2], acc[mt][nt][3]);
        }
    }
}

// ---------------- gather2 fused: agg2 = gather(t16) + r2h + bias; BN2 stats ----------------
__global__ void __launch_bounds__(256) gather2_fused_kernel(
    const __half* __restrict__ feat, const int* __restrict__ off,
    const int* __restrict__ csrc, const __half* __restrict__ r2h,
    const float* __restrict__ bias, float* __restrict__ out, int N,
    double* __restrict__ sumd, double* __restrict__ sqd)
{
    __shared__ float shs[32], shq[32];
    int tid = threadIdx.x;
    if (tid < 32) { shs[tid] = 0.f; shq[tid] = 0.f; }
    __syncthreads();

    int gid = blockIdx.x * 256 + tid;
    int w = gid >> 2;
    int j = gid & 3;
    bool valid = (w < N);

    float v[8];
#pragma unroll
    for (int q = 0; q < 8; q++) v[q] = 0.f;

    if (valid) {
        int end = __ldg(&off[w]);
        int beg = (w == 0) ? 0 : __ldg(&off[w - 1]);
        const __half* base = feat + j * 8;
        for (int k = beg; k < end; k++) {
            int s0 = __ldg(&csrc[k]);
            uint4 r0 = *(const uint4*)(base + (size_t)s0 * 32);
            float2 f;
            f = __half22float2(*(__half2*)&r0.x); v[0] += f.x; v[1] += f.y;
            f = __half22float2(*(__half2*)&r0.y); v[2] += f.x; v[3] += f.y;
            f = __half22float2(*(__half2*)&r0.z); v[4] += f.x; v[5] += f.y;
            f = __half22float2(*(__half2*)&r0.w); v[6] += f.x; v[7] += f.y;
        }
        uint4 rr = *(const uint4*)(r2h + (size_t)w * 32 + j * 8);
        const float* bp = bias + j * 8;
        const unsigned* pr = (const unsigned*)&rr;
#pragma unroll
        for (int q = 0; q < 4; q++) {
            float2 f = __half22float2(*(const __half2*)&pr[q]);
            v[q * 2 + 0] += f.x + __ldg(bp + q * 2 + 0);
            v[q * 2 + 1] += f.y + __ldg(bp + q * 2 + 1);
        }
        float* op = out + (size_t)w * D_OUT + j * 8;
        *(float4*)(op + 0) = make_float4(v[0], v[1], v[2], v[3]);
        *(float4*)(op + 4) = make_float4(v[4], v[5], v[6], v[7]);
    }

    float s[8], q[8];
#pragma unroll
    for (int t = 0; t < 8; t++) {
        s[t] = valid ? v[t] : 0.f;
        q[t] = valid ? v[t] * v[t] : 0.f;
    }
#pragma unroll
    for (int msk = 4; msk < 32; msk <<= 1)
#pragma unroll
        for (int t = 0; t < 8; t++) {
            s[t] += __shfl_xor_sync(0xffffffffu, s[t], msk);
            q[t] += __shfl_xor_sync(0xffffffffu, q[t], msk);
        }
    if ((tid & 31) < 4) {
#pragma unroll
        for (int t = 0; t < 8; t++) {
            atomicAdd(&shs[j * 8 + t], s[t]);
            atomicAdd(&shq[j * 8 + t], q[t]);
        }
    }
    __syncthreads();
    if (tid < 32) {
        atomicAdd(&sumd[tid], (double)shs[tid]);
        atomicAdd(&sqd[tid], (double)shq[tid]);
    }
}

// ---------------- final normalize/relu with in-block BN2 coefficients ----------------
__global__ void __launch_bounds__(256) bn_relu4_kernel(
    const float4* __restrict__ in, float4* __restrict__ out, long long n4,
    const double* __restrict__ stats, const float* __restrict__ gamma,
    const float* __restrict__ beta, float invM)
{
    __shared__ float sscale[32], sshift[32];
    if (threadIdx.x < 32) {
        int c = threadIdx.x;
        double mu = stats[c] * (double)invM;
        double var = stats[32 + c] * (double)invM - mu * mu;
        float s = gamma[c] * rsqrtf((float)var + 1e-5f);
        sscale[c] = s;
        sshift[c] = beta[c] - (float)mu * s;
    }
    __syncthreads();
    long long i = (long long)blockIdx.x * blockDim.x + threadIdx.x;
    long long stride = (long long)gridDim.x * blockDim.x;
    for (; i < n4; i += stride) {
        int c = (int)((i << 2) & 31);
        float4 v = in[i];
        v.x = fmaxf(fmaf(v.x, sscale[c + 0], sshift[c + 0]), 0.f);
        v.y = fmaxf(fmaf(v.y, sscale[c + 1], sshift[c + 1]), 0.f);
        v.z = fmaxf(fmaf(v.z, sscale[c + 2], sshift[c + 2]), 0.f);
        v.w = fmaxf(fmaf(v.w, sscale[c + 3], sshift[c + 3]), 0.f);
        out[i] = v;
    }
}

static inline int ceil_div_i(int a, int b) { return (a + b - 1) / b; }

// ---------------- launch ----------------
extern "C" void kernel_launch(void* const* d_in, const int* in_sizes, int n_in,
                              void* d_out, int out_size)
{
    const float* x      = (const float*)d_in[0];
    const void*  ei     = d_in[1];
    const float* Wrel1  = (const float*)d_in[2];
    const float* brel1  = (const float*)d_in[3];
    const float* Wroot1 = (const float*)d_in[4];
    const float* gamma1 = (const float*)d_in[5];
    const float* beta1  = (const float*)d_in[6];
    const float* Wrel2  = (const float*)d_in[7];
    const float* brel2  = (const float*)d_in[8];
    const float* Wroot2 = (const float*)d_in[9];
    const float* gamma2 = (const float*)d_in[10];
    const float* beta2  = (const float*)d_in[11];

    const int N = in_sizes[0] / D_IN;
    const int E = in_sizes[1] / 2;

    float *agg2;
    __half *x16, *agg1h, *h1h, *r2h, *t16, *w1hT, *w2hT;
    double* stats;
    int *off, *csrc;
    cudaGetSymbolAddress((void**)&x16, g_x16);
    cudaGetSymbolAddress((void**)&agg1h, g_agg1h);
    cudaGetSymbolAddress((void**)&h1h, g_h1h);
    cudaGetSymbolAddress((void**)&r2h, g_r2h);
    cudaGetSymbolAddress((void**)&t16, g_t16);
    cudaGetSymbolAddress((void**)&agg2, g_agg2);
    cudaGetSymbolAddress((void**)&stats, g_stats);
    cudaGetSymbolAddress((void**)&w1hT, g_w1hT);
    cudaGetSymbolAddress((void**)&w2hT, g_w2hT);
    cudaGetSymbolAddress((void**)&off, g_off);
    cudaGetSymbolAddress((void**)&csrc, g_csrc);

    const int nchunks = ceil_div_i(N, SCHUNK);
    const int eblocks = ceil_div_i(E, 256);
    const float invM = 1.0f / (float)N;

    // streams/events created on first (non-captured) call; reused afterwards
    static cudaStream_t s2 = nullptr;
    static cudaEvent_t evStart = nullptr, evJoin = nullptr;
    if (!s2) {
        cudaStreamCreateWithFlags(&s2, cudaStreamNonBlocking);
        cudaEventCreateWithFlags(&evStart, cudaEventDisableTiming);
        cudaEventCreateWithFlags(&evJoin, cudaEventDisableTiming);
    }

    // ---- fork: CSR chain on main, data-prep chain on s2 ----
    cudaEventRecord(evStart, 0);
    cudaStreamWaitEvent(s2, evStart, 0);

    init_kernel<<<1024, 256, 0, s2>>>(stats, x, x16, (long long)N * D_IN / 2,
                                      Wrel1, Wroot1, Wrel2, Wroot2, w1hT, w2hT);
    cudaEventRecord(evJoin, s2);

    zero_off_kernel<<<128, 256>>>((const int*)ei, E, off, N);
    hist_kernel<<<eblocks, 256>>>(ei, E, off);
    scan_lookback_kernel<<<nchunks, SCHUNK>>>(off, N);
    fill_kernel<<<eblocks, 256>>>(ei, E, off, csrc);

    // ---- join ----
    cudaStreamWaitEvent(0, evJoin, 0);
    gather1_kernel<<<ceil_div_i(N * 16, 256), 256>>>(x16, off, csrc, agg1h, N);
    gemm1_kernel<<<ceil_div_i(N, 128), 256>>>(
        agg1h, x16, w1hT, brel1, h1h, N, stats, stats + 128);

    gemm2_kernel<<<ceil_div_i(N, 128), 256>>>(h1h, w2hT, r2h, t16, N,
                                              stats, gamma1, beta1, invM);
    gather2_fused_kernel<<<ceil_div_i(N * 4, 256), 256>>>(
        t16, off, csrc, r2h, brel2, agg2, N, stats + 256, stats + 288);

    bn_relu4_kernel<<<1024, 256>>>((const float4*)agg2, (float4*)d_out,
                                   (long long)N * D_OUT / 4,
                                   stats + 256, gamma2, beta2, invM);
}